// round 4
// baseline (speedup 1.0000x reference)
#include <cuda_runtime.h>
#include <math.h>

#define NN     200000
#define EE     8192
#define HH     64
#define TEDIM  32
#define EADIM  32
#define KF     192     // 2H + EA + TE
#define G4     256     // 4H
#define DFEAT  128
#define KZ     192     // H + D_FEAT
#define AA     50
#define SCAN_BLOCKS 148
#define NGROUP 8
#define NSTREAM (SCAN_BLOCKS * NGROUP)   // 1184 concurrent event streams

// prep kernel role partition
#define PREP_INIT_BLOCKS 4096
#define PREP_SEQ_BLOCKS  128
#define PREP_FUSE_BLOCKS 40
#define PREP_BLOCKS (PREP_INIT_BLOCKS + PREP_SEQ_BLOCKS + PREP_FUSE_BLOCKS)

// ---------------- device scratch (static, no runtime alloc) ----------------
__device__ float g_h[(size_t)NN * HH];     // node memory
__device__ float g_c[(size_t)NN * HH];     // LSTM cell state
__device__ int   g_done[NN];               // per-node completed-endpoint counter
__device__ int2  g_pairs[EE];              // (src, dst)
__device__ int   g_seq[2 * EE];            // per-endpoint rank among same-node endpoints
__device__ float g_Wf[KZ * AA];            // fused W_emb @ W_cls
__device__ float g_bf[AA];                 // fused bias

// ---------------- helpers ----------------
__device__ __forceinline__ int ld_acq(const int* p) {
    int v;
    asm volatile("ld.global.acquire.gpu.b32 %0, [%1];" : "=r"(v) : "l"(p));
    return v;
}
__device__ __forceinline__ void st_rel(int* p, int v) {
    asm volatile("st.global.release.gpu.b32 [%0], %1;" :: "l"(p), "r"(v) : "memory");
}
__device__ __forceinline__ void bar_group(int g) {
    asm volatile("bar.sync %0, 64;" :: "r"(g + 1) : "memory");
}
__device__ __forceinline__ float sigf(float x) {
    return 1.f / (1.f + __expf(-x));
}

// ---------------- kernel 1: prep (init + seq + fuse, role by blockIdx) -----
__global__ void __launch_bounds__(256) prep_kernel(
    const int* __restrict__ eidx,
    const float* __restrict__ W_emb, const float* __restrict__ W_cls,
    const float* __restrict__ b_emb, const float* __restrict__ b_cls)
{
    int b = blockIdx.x;
    int t = threadIdx.x;

    if (b < PREP_INIT_BLOCKS) {
        // ---- init role: zero h/c of touched nodes, build pairs, clear done
        int idx = b * 256 + t;            // [0, 2*EE*64)
        int n = idx >> 6;                 // endpoint id
        int i = idx & 63;
        int e = n & (EE - 1);
        int s = n >> 13;
        int u = eidx[s * EE + e];
        g_h[(size_t)u * HH + i] = 0.f;
        g_c[(size_t)u * HH + i] = 0.f;
        if (i == 0) {
            g_done[u] = 0;
            if (s == 0) g_pairs[e] = make_int2(eidx[e], eidx[EE + e]);
        }
    } else if (b < PREP_INIT_BLOCKS + PREP_SEQ_BLOCKS) {
        // ---- seq role: per-endpoint rank among earlier same-node endpoints
        extern __shared__ int2 sp[];
        int bb = b - PREP_INIT_BLOCKS;
        for (int i = t; i < EE; i += 256)
            sp[i] = make_int2(eidx[i], eidx[EE + i]);
        __syncthreads();
        int lane = t & 31, w = t >> 5;
        for (int n = bb * 8 + w; n < 2 * EE; n += PREP_SEQ_BLOCKS * 8) {
            int e = n >> 1, s = n & 1;
            int2 pe = sp[e];
            int u = s ? pe.y : pe.x;
            int cnt = 0;
            for (int j = lane; j < e; j += 32) {
                int2 p = sp[j];
                cnt += (p.x == u) + (p.y == u);
            }
            #pragma unroll
            for (int off = 16; off > 0; off >>= 1)
                cnt += __shfl_down_sync(0xffffffffu, cnt, off);
            if (lane == 0) g_seq[n] = cnt;
        }
    } else {
        // ---- fuse role: Wf = W_emb @ W_cls, bf = b_emb @ W_cls + b_cls
        int bb = b - PREP_INIT_BLOCKS - PREP_SEQ_BLOCKS;
        int idx = bb * 256 + t;
        if (idx < KZ * AA) {
            int k = idx / AA, a = idx % AA;
            float s = 0.f;
            #pragma unroll 8
            for (int c = 0; c < HH; c++) s = fmaf(W_emb[k * HH + c], W_cls[c * AA + a], s);
            g_Wf[idx] = s;
        } else if (idx < KZ * AA + AA) {
            int a = idx - KZ * AA;
            float s = b_cls[a];
            for (int c = 0; c < HH; c++) s = fmaf(b_emb[c], W_cls[c * AA + a], s);
            g_bf[a] = s;
        }
    }
}

// ---------------- kernel 2: persistent dataflow scan, 8 groups/block ------
// smem float offsets
#define O_WPM    0              // float2[64*64]: (w1+w2, w1-w2) for k<64, per col
#define O_WC     8192           // float2[32*64]: comm weights, k-paired
#define O_WIH    12288          // permuted [k*64+col]*4+gate
#define O_WHH    28672
#define O_BMSG   45056
#define O_BLSTM  45120
#define O_TW     45376
#define O_TB     45408
#define O_GRP    45440          // per-group: 448 floats
//   group layout: sHp float2[64] | sSD float2[64] | sComm float[64] | sMp float2[64]
#define GRP_F    448
#define SCAN_SMEM_F (O_GRP + NGROUP * GRP_F)   // 49024 floats = 191.5 KB

__global__ void __launch_bounds__(512, 1) scan_kernel(
    const float* __restrict__ Wmsg, const float* __restrict__ bmsg,
    const float* __restrict__ Wih,  const float* __restrict__ Whh,
    const float* __restrict__ blstm, const float* __restrict__ tw,
    const float* __restrict__ tb,   const float* __restrict__ eattr,
    const float* __restrict__ etime)
{
    extern __shared__ float sm[];
    float2* sWpm  = (float2*)(sm + O_WPM);
    float2* sWc   = (float2*)(sm + O_WC);
    float*  sWihP = sm + O_WIH;
    float*  sWhhP = sm + O_WHH;
    float*  sbmsg = sm + O_BMSG;
    float*  sblstm= sm + O_BLSTM;
    float*  stw   = sm + O_TW;
    float*  stb   = sm + O_TB;

    int t = threadIdx.x;
    int g = t >> 6, lt = t & 63;

    float* grp = sm + O_GRP + g * GRP_F;
    float2* sHp   = (float2*)grp;            // 128 floats
    float2* sSD   = (float2*)(grp + 128);    // 128 floats
    float*  sComm = grp + 256;               // 64 floats
    float2* sMp   = (float2*)(grp + 320);    // 128 floats

    // ---- load + transform weights (whole block) ----
    for (int i = t; i < 64 * 64; i += 512) {
        int k = i >> 6, col = i & 63;
        float w1 = Wmsg[k * HH + col];
        float w2 = Wmsg[(64 + k) * HH + col];
        sWpm[i] = make_float2(w1 + w2, w1 - w2);
    }
    for (int i = t; i < 32 * 64; i += 512) {
        int k2 = i >> 6, col = i & 63;
        sWc[i] = make_float2(Wmsg[(128 + 2 * k2) * HH + col],
                             Wmsg[(129 + 2 * k2) * HH + col]);
    }
    for (int i = t; i < HH * G4; i += 512) {
        int k = i >> 8, j = i & 255;
        int p = ((k << 6) + (j & 63)) * 4 + (j >> 6);
        sWihP[p] = Wih[i];
        sWhhP[p] = Whh[i];
    }
    if (t < HH)    sbmsg[t]  = bmsg[t];
    if (t < G4)    sblstm[t] = blstm[t];
    if (t < TEDIM) { stw[t] = tw[t]; stb[t] = tb[t]; }
    __syncthreads();

    for (int e = blockIdx.x * NGROUP + g; e < EE; e += NSTREAM) {
        int2 pr = g_pairs[e];
        int s0 = g_seq[2 * e], s1 = g_seq[2 * e + 1];

        // every thread spins itself (acquire); bounded to avoid hang on a bug
        {
            int guard = 0;
            while ((ld_acq(&g_done[pr.x]) != s0 || ld_acq(&g_done[pr.y]) != s1)
                   && ++guard < (1 << 18)) {}
        }

        // ---- load state (L2-coherent) + build shared operands ----
        float hs = __ldcg(&g_h[(size_t)pr.x * HH + lt]);
        float hd = __ldcg(&g_h[(size_t)pr.y * HH + lt]);
        float cs = __ldcg(&g_c[(size_t)pr.x * HH + lt]);
        float cd = __ldcg(&g_c[(size_t)pr.y * HH + lt]);
        sHp[lt] = make_float2(hs, hd);
        sSD[lt] = make_float2(hs + hd, hs - hd);
        if (lt < EADIM) {
            sComm[lt] = eattr[e * EADIM + lt];
        } else {
            int i = lt - EADIM;
            float tv = __ldg(&etime[e]);
            sComm[lt] = cosf(tv * stw[i] + stb[i]);
        }
        bar_group(g);

        // ---- gemm1 (sum/diff form): thread t -> col t ----
        // a0 = Σ hd·w1 + hs·w2 + comm = c + (u-v)/2 ; a1 = c + (u+v)/2
        float u = 0.f, v = 0.f, ac = sbmsg[lt];
        #pragma unroll 8
        for (int k = 0; k < 64; k++) {
            float2 sd = sSD[k];
            float2 w  = sWpm[k * 64 + lt];
            u = fmaf(sd.x, w.x, u);
            v = fmaf(sd.y, w.y, v);
        }
        const float2* cm2 = (const float2*)sComm;
        #pragma unroll 8
        for (int k2 = 0; k2 < 32; k2++) {
            float2 c = cm2[k2];
            float2 w = sWc[k2 * 64 + lt];
            ac = fmaf(c.x, w.x, ac);
            ac = fmaf(c.y, w.y, ac);
        }
        float m0 = fmaxf(ac + 0.5f * (u - v), 0.f);   // row0 (src update)
        float m1 = fmaxf(ac + 0.5f * (u + v), 0.f);   // row1 (dst update)
        sMp[lt] = make_float2(m0, m1);
        bar_group(g);

        // ---- gemm2: gates = m@Wih + hp@Whh + b. thread t -> cell col t ----
        float ac00 = sblstm[lt],       ac01 = sblstm[lt + 64];
        float ac02 = sblstm[lt + 128], ac03 = sblstm[lt + 192];
        float ac10 = ac00, ac11 = ac01, ac12 = ac02, ac13 = ac03;
        #pragma unroll 8
        for (int k = 0; k < 64; k++) {
            float2 m = sMp[k];
            float2 h = sHp[k];
            float4 wi = *(const float4*)&sWihP[(k * 64 + lt) * 4];
            float4 wh = *(const float4*)&sWhhP[(k * 64 + lt) * 4];
            ac00 = fmaf(m.x, wi.x, ac00); ac01 = fmaf(m.x, wi.y, ac01);
            ac02 = fmaf(m.x, wi.z, ac02); ac03 = fmaf(m.x, wi.w, ac03);
            ac10 = fmaf(m.y, wi.x, ac10); ac11 = fmaf(m.y, wi.y, ac11);
            ac12 = fmaf(m.y, wi.z, ac12); ac13 = fmaf(m.y, wi.w, ac13);
            ac00 = fmaf(h.x, wh.x, ac00); ac01 = fmaf(h.x, wh.y, ac01);
            ac02 = fmaf(h.x, wh.z, ac02); ac03 = fmaf(h.x, wh.w, ac03);
            ac10 = fmaf(h.y, wh.x, ac10); ac11 = fmaf(h.y, wh.y, ac11);
            ac12 = fmaf(h.y, wh.z, ac12); ac13 = fmaf(h.y, wh.w, ac13);
        }

        // ---- LSTM elementwise in registers + state write ----
        bool selfloop = (pr.x == pr.y);
        {   // row 1 (dst) — always written (JAX last-write-wins)
            float cn = sigf(ac11) * cd + sigf(ac10) * tanhf(ac12);
            float hn = sigf(ac13) * tanhf(cn);
            __stcg(&g_h[(size_t)pr.y * HH + lt], hn);
            __stcg(&g_c[(size_t)pr.y * HH + lt], cn);
        }
        if (!selfloop) {  // row 0 (src)
            float cn = sigf(ac01) * cs + sigf(ac00) * tanhf(ac02);
            float hn = sigf(ac03) * tanhf(cn);
            __stcg(&g_h[(size_t)pr.x * HH + lt], hn);
            __stcg(&g_c[(size_t)pr.x * HH + lt], cn);
        }
        bar_group(g);

        if (lt == 0) {
            __threadfence();
            if (selfloop) {
                st_rel(&g_done[pr.x], s0 + 2);
            } else {
                st_rel(&g_done[pr.x], s0 + 1);
                st_rel(&g_done[pr.y], s1 + 1);
            }
        }
    }
}

// ---------------- kernel 3: epilogue  logits[e] = [h[dst]||x[dst]] @ Wf + bf
__global__ void __launch_bounds__(256) epilogue_kernel(const float* __restrict__ x,
                                                       const int* __restrict__ eidx,
                                                       float* __restrict__ out) {
    __shared__ float sWf[KZ * AA];
    __shared__ float sbf[AA];
    __shared__ float sCat[8][KZ];
    int t = threadIdx.x;
    for (int i = t; i < KZ * AA; i += 256) sWf[i] = g_Wf[i];
    if (t < AA) sbf[t] = g_bf[t];
    __syncthreads();
    int lane = t & 31, w = t >> 5;
    for (int e = blockIdx.x * 8 + w; e < EE; e += gridDim.x * 8) {
        int dst = eidx[EE + e];
        #pragma unroll
        for (int q = 0; q < 6; q++) {
            int k = lane + q * 32;
            sCat[w][k] = (k < HH) ? g_h[(size_t)dst * HH + k]
                                  : x[(size_t)dst * DFEAT + (k - HH)];
        }
        __syncwarp();
        float a0 = sbf[lane];
        float a1 = (lane < AA - 32) ? sbf[lane + 32] : 0.f;
        #pragma unroll 4
        for (int k = 0; k < KZ; k++) {
            float v = sCat[w][k];
            a0 = fmaf(v, sWf[k * AA + lane], a0);
            if (lane < AA - 32) a1 = fmaf(v, sWf[k * AA + lane + 32], a1);
        }
        out[(size_t)e * AA + lane] = a0;
        if (lane < AA - 32) out[(size_t)e * AA + lane + 32] = a1;
        __syncwarp();
    }
}

// ---------------- launch ----------------
extern "C" void kernel_launch(void* const* d_in, const int* in_sizes, int n_in,
                              void* d_out, int out_size) {
    const float* x      = (const float*)d_in[0];
    const int*   eidx   = (const int*)  d_in[1];
    const float* eattr  = (const float*)d_in[2];
    const float* etime  = (const float*)d_in[3];
    const float* time_w = (const float*)d_in[4];
    const float* time_b = (const float*)d_in[5];
    const float* W_msg  = (const float*)d_in[6];
    const float* b_msg  = (const float*)d_in[7];
    const float* W_ih   = (const float*)d_in[8];
    const float* W_hh   = (const float*)d_in[9];
    const float* b_lstm = (const float*)d_in[10];
    const float* W_emb  = (const float*)d_in[11];
    const float* b_emb  = (const float*)d_in[12];
    const float* W_cls  = (const float*)d_in[13];
    const float* b_cls  = (const float*)d_in[14];
    float* out = (float*)d_out;

    cudaFuncSetAttribute(prep_kernel, cudaFuncAttributeMaxDynamicSharedMemorySize,
                         EE * (int)sizeof(int2));
    cudaFuncSetAttribute(scan_kernel, cudaFuncAttributeMaxDynamicSharedMemorySize,
                         SCAN_SMEM_F * (int)sizeof(float));

    prep_kernel<<<PREP_BLOCKS, 256, EE * sizeof(int2)>>>(eidx, W_emb, W_cls, b_emb, b_cls);
    scan_kernel<<<SCAN_BLOCKS, 512, SCAN_SMEM_F * sizeof(float)>>>(
        W_msg, b_msg, W_ih, W_hh, b_lstm, time_w, time_b, eattr, etime);
    epilogue_kernel<<<256, 256>>>(x, eidx, out);
}

// round 5
// speedup vs baseline: 1.3604x; 1.3604x over previous
#include <cuda_runtime.h>
#include <math.h>

#define NN     200000
#define EE     8192
#define HH     64
#define TEDIM  32
#define EADIM  32
#define KF     192     // 2H + EA + TE
#define G4     256     // 4H
#define DFEAT  128
#define KZ     192     // H + D_FEAT
#define AA     50
#define SCAN_BLOCKS 148
#define NGROUP 8
#define NSTREAM (SCAN_BLOCKS * NGROUP)   // 1184 concurrent event streams

// misc kernel roles: [0,64) zero done + build pairs ; [64,104) fuse
#define MISC_ZERO_BLOCKS 64
#define MISC_FUSE_BLOCKS 40
#define MISC_BLOCKS (MISC_ZERO_BLOCKS + MISC_FUSE_BLOCKS)

// ---------------- device scratch (static, no runtime alloc) ----------------
__device__ float g_h[(size_t)NN * HH];     // node memory (never pre-zeroed: seq==0 => use 0)
__device__ float g_c[(size_t)NN * HH];     // LSTM cell state
__device__ int   g_done[NN];               // per-node completed-endpoint counter
__device__ int2  g_pairs[EE];              // (src, dst)
__device__ int   g_seq[2 * EE];            // per-endpoint rank among same-node endpoints
__device__ float g_Wf[KZ * AA];            // fused W_emb @ W_cls
__device__ float g_bf[AA];                 // fused bias

// ---------------- helpers ----------------
__device__ __forceinline__ int ld_acq(const int* p) {
    int v;
    asm volatile("ld.global.acquire.gpu.b32 %0, [%1];" : "=r"(v) : "l"(p));
    return v;
}
__device__ __forceinline__ void st_rel(int* p, int v) {
    asm volatile("st.global.release.gpu.b32 [%0], %1;" :: "l"(p), "r"(v) : "memory");
}
__device__ __forceinline__ void bar_group(int g) {
    asm volatile("bar.sync %0, 64;" :: "r"(g + 1) : "memory");
}
__device__ __forceinline__ float sigf(float x) {
    return 1.f / (1.f + __expf(-x));
}

// ---------------- kernel 1: misc (zero done + pairs + fuse) — NO smem -----
__global__ void __launch_bounds__(256) misc_kernel(
    const int* __restrict__ eidx,
    const float* __restrict__ W_emb, const float* __restrict__ W_cls,
    const float* __restrict__ b_emb, const float* __restrict__ b_cls)
{
    int b = blockIdx.x;
    int t = threadIdx.x;
    if (b < MISC_ZERO_BLOCKS) {
        int n = b * 256 + t;              // endpoint id [0, 2*EE)
        int u = eidx[n];                  // eidx is [2, EE] row-major: n covers both rows
        g_done[u] = 0;                    // racing same-value writes: benign
        if (n < EE) g_pairs[n] = make_int2(eidx[n], eidx[EE + n]);
    } else {
        int idx = (b - MISC_ZERO_BLOCKS) * 256 + t;
        if (idx < KZ * AA) {
            int k = idx / AA, a = idx % AA;
            float s = 0.f;
            #pragma unroll 8
            for (int c = 0; c < HH; c++) s = fmaf(W_emb[k * HH + c], W_cls[c * AA + a], s);
            g_Wf[idx] = s;
        } else if (idx < KZ * AA + AA) {
            int a = idx - KZ * AA;
            float s = b_cls[a];
            for (int c = 0; c < HH; c++) s = fmaf(b_emb[c], W_cls[c * AA + a], s);
            g_bf[a] = s;
        }
    }
}

// ---------------- kernel 2: per-endpoint sequence numbers (brute, smem) ----
__global__ void __launch_bounds__(256) seq_kernel(const int* __restrict__ eidx) {
    extern __shared__ int2 sp[];
    int t = threadIdx.x;
    for (int i = t; i < EE; i += 256)
        sp[i] = make_int2(eidx[i], eidx[EE + i]);
    __syncthreads();
    int lane = t & 31, w = t >> 5;
    for (int n = blockIdx.x * 8 + w; n < 2 * EE; n += gridDim.x * 8) {
        int e = n >> 1, s = n & 1;
        int2 pe = sp[e];
        int u = s ? pe.y : pe.x;
        int cnt = 0;
        for (int j = lane; j < e; j += 32) {
            int2 p = sp[j];
            cnt += (p.x == u) + (p.y == u);
        }
        #pragma unroll
        for (int off = 16; off > 0; off >>= 1)
            cnt += __shfl_down_sync(0xffffffffu, cnt, off);
        if (lane == 0) g_seq[n] = cnt;
    }
}

// ---------------- kernel 3: persistent dataflow scan, 8 groups/block ------
// smem float offsets
#define O_WPM    0              // float2[64*64]: (w1+w2, w1-w2) for k<64, per col
#define O_WC     8192           // float2[32*64]: comm weights, k-paired
#define O_WIH    12288          // permuted [k*64+col]*4+gate
#define O_WHH    28672
#define O_BMSG   45056
#define O_BLSTM  45120
#define O_TW     45376
#define O_TB     45408
#define O_GRP    45440          // per-group: 448 floats
#define GRP_F    448
#define SCAN_SMEM_F (O_GRP + NGROUP * GRP_F)   // 49024 floats = 191.5 KB

__global__ void __launch_bounds__(512, 1) scan_kernel(
    const float* __restrict__ Wmsg, const float* __restrict__ bmsg,
    const float* __restrict__ Wih,  const float* __restrict__ Whh,
    const float* __restrict__ blstm, const float* __restrict__ tw,
    const float* __restrict__ tb,   const float* __restrict__ eattr,
    const float* __restrict__ etime)
{
    extern __shared__ float sm[];
    float2* sWpm  = (float2*)(sm + O_WPM);
    float2* sWc   = (float2*)(sm + O_WC);
    float*  sWihP = sm + O_WIH;
    float*  sWhhP = sm + O_WHH;
    float*  sbmsg = sm + O_BMSG;
    float*  sblstm= sm + O_BLSTM;
    float*  stw   = sm + O_TW;
    float*  stb   = sm + O_TB;

    int t = threadIdx.x;
    int g = t >> 6, lt = t & 63;

    float* grp = sm + O_GRP + g * GRP_F;
    float2* sHp   = (float2*)grp;            // 128 floats
    float2* sSD   = (float2*)(grp + 128);    // 128 floats
    float*  sComm = grp + 256;               // 64 floats
    float2* sMp   = (float2*)(grp + 320);    // 128 floats

    // ---- load + transform weights (whole block) ----
    for (int i = t; i < 64 * 64; i += 512) {
        int k = i >> 6, col = i & 63;
        float w1 = Wmsg[k * HH + col];
        float w2 = Wmsg[(64 + k) * HH + col];
        sWpm[i] = make_float2(w1 + w2, w1 - w2);
    }
    for (int i = t; i < 32 * 64; i += 512) {
        int k2 = i >> 6, col = i & 63;
        sWc[i] = make_float2(Wmsg[(128 + 2 * k2) * HH + col],
                             Wmsg[(129 + 2 * k2) * HH + col]);
    }
    for (int i = t; i < HH * G4; i += 512) {
        int k = i >> 8, j = i & 255;
        int p = ((k << 6) + (j & 63)) * 4 + (j >> 6);
        sWihP[p] = Wih[i];
        sWhhP[p] = Whh[i];
    }
    if (t < HH)    sbmsg[t]  = bmsg[t];
    if (t < G4)    sblstm[t] = blstm[t];
    if (t < TEDIM) { stw[t] = tw[t]; stb[t] = tb[t]; }
    __syncthreads();

    for (int e = blockIdx.x * NGROUP + g; e < EE; e += NSTREAM) {
        int2 pr = g_pairs[e];
        int s0 = g_seq[2 * e], s1 = g_seq[2 * e + 1];
        bool w0 = (s0 > 0), w1 = (s1 > 0);   // any predecessor this replay?

        if (w0 || w1) {      // dependency spin (bounded); skipped for first-touch
            int guard = 0;
            while (((w0 && ld_acq(&g_done[pr.x]) != s0) ||
                    (w1 && ld_acq(&g_done[pr.y]) != s1)) && ++guard < (1 << 18)) {}
        }

        // ---- state: load only if written earlier this replay, else 0 ----
        float hs = w0 ? __ldcg(&g_h[(size_t)pr.x * HH + lt]) : 0.f;
        float cs = w0 ? __ldcg(&g_c[(size_t)pr.x * HH + lt]) : 0.f;
        float hd = w1 ? __ldcg(&g_h[(size_t)pr.y * HH + lt]) : 0.f;
        float cd = w1 ? __ldcg(&g_c[(size_t)pr.y * HH + lt]) : 0.f;
        sHp[lt] = make_float2(hs, hd);
        sSD[lt] = make_float2(hs + hd, hs - hd);
        if (lt < EADIM) {
            sComm[lt] = eattr[e * EADIM + lt];
        } else {
            int i = lt - EADIM;
            float tv = __ldg(&etime[e]);
            sComm[lt] = cosf(tv * stw[i] + stb[i]);
        }
        bar_group(g);

        // ---- gemm1 (sum/diff form): thread t -> col t ----
        float u = 0.f, v = 0.f, ac = sbmsg[lt];
        #pragma unroll 8
        for (int k = 0; k < 64; k++) {
            float2 sd = sSD[k];
            float2 w  = sWpm[k * 64 + lt];
            u = fmaf(sd.x, w.x, u);
            v = fmaf(sd.y, w.y, v);
        }
        const float2* cm2 = (const float2*)sComm;
        #pragma unroll 8
        for (int k2 = 0; k2 < 32; k2++) {
            float2 c = cm2[k2];
            float2 w = sWc[k2 * 64 + lt];
            ac = fmaf(c.x, w.x, ac);
            ac = fmaf(c.y, w.y, ac);
        }
        float m0 = fmaxf(ac + 0.5f * (u - v), 0.f);   // row0 (src update)
        float m1 = fmaxf(ac + 0.5f * (u + v), 0.f);   // row1 (dst update)
        sMp[lt] = make_float2(m0, m1);
        bar_group(g);

        // ---- gemm2: gates = m@Wih + hp@Whh + b. thread t -> cell col t ----
        float ac00 = sblstm[lt],       ac01 = sblstm[lt + 64];
        float ac02 = sblstm[lt + 128], ac03 = sblstm[lt + 192];
        float ac10 = ac00, ac11 = ac01, ac12 = ac02, ac13 = ac03;
        #pragma unroll 8
        for (int k = 0; k < 64; k++) {
            float2 m = sMp[k];
            float2 h = sHp[k];
            float4 wi = *(const float4*)&sWihP[(k * 64 + lt) * 4];
            float4 wh = *(const float4*)&sWhhP[(k * 64 + lt) * 4];
            ac00 = fmaf(m.x, wi.x, ac00); ac01 = fmaf(m.x, wi.y, ac01);
            ac02 = fmaf(m.x, wi.z, ac02); ac03 = fmaf(m.x, wi.w, ac03);
            ac10 = fmaf(m.y, wi.x, ac10); ac11 = fmaf(m.y, wi.y, ac11);
            ac12 = fmaf(m.y, wi.z, ac12); ac13 = fmaf(m.y, wi.w, ac13);
            ac00 = fmaf(h.x, wh.x, ac00); ac01 = fmaf(h.x, wh.y, ac01);
            ac02 = fmaf(h.x, wh.z, ac02); ac03 = fmaf(h.x, wh.w, ac03);
            ac10 = fmaf(h.y, wh.x, ac10); ac11 = fmaf(h.y, wh.y, ac11);
            ac12 = fmaf(h.y, wh.z, ac12); ac13 = fmaf(h.y, wh.w, ac13);
        }

        // ---- LSTM elementwise in registers + state write ----
        bool selfloop = (pr.x == pr.y);
        {   // row 1 (dst) — always written (JAX last-write-wins)
            float cn = sigf(ac11) * cd + sigf(ac10) * tanhf(ac12);
            float hn = sigf(ac13) * tanhf(cn);
            __stcg(&g_h[(size_t)pr.y * HH + lt], hn);
            __stcg(&g_c[(size_t)pr.y * HH + lt], cn);
        }
        if (!selfloop) {  // row 0 (src)
            float cn = sigf(ac01) * cs + sigf(ac00) * tanhf(ac02);
            float hn = sigf(ac03) * tanhf(cn);
            __stcg(&g_h[(size_t)pr.x * HH + lt], hn);
            __stcg(&g_c[(size_t)pr.x * HH + lt], cn);
        }
        bar_group(g);

        if (lt == 0) {
            __threadfence();
            if (selfloop) {
                st_rel(&g_done[pr.x], s0 + 2);
            } else {
                st_rel(&g_done[pr.x], s0 + 1);
                st_rel(&g_done[pr.y], s1 + 1);
            }
        }
    }
}

// ---------------- kernel 4: epilogue  logits[e] = [h[dst]||x[dst]] @ Wf + bf
__global__ void __launch_bounds__(256) epilogue_kernel(const float* __restrict__ x,
                                                       const int* __restrict__ eidx,
                                                       float* __restrict__ out) {
    __shared__ float sWf[KZ * AA];
    __shared__ float sbf[AA];
    __shared__ float sCat[8][KZ];
    int t = threadIdx.x;
    for (int i = t; i < KZ * AA; i += 256) sWf[i] = g_Wf[i];
    if (t < AA) sbf[t] = g_bf[t];
    __syncthreads();
    int lane = t & 31, w = t >> 5;
    for (int e = blockIdx.x * 8 + w; e < EE; e += gridDim.x * 8) {
        int dst = eidx[EE + e];
        #pragma unroll
        for (int q = 0; q < 6; q++) {
            int k = lane + q * 32;
            sCat[w][k] = (k < HH) ? g_h[(size_t)dst * HH + k]
                                  : x[(size_t)dst * DFEAT + (k - HH)];
        }
        __syncwarp();
        float a0 = sbf[lane];
        float a1 = (lane < AA - 32) ? sbf[lane + 32] : 0.f;
        #pragma unroll 4
        for (int k = 0; k < KZ; k++) {
            float v = sCat[w][k];
            a0 = fmaf(v, sWf[k * AA + lane], a0);
            if (lane < AA - 32) a1 = fmaf(v, sWf[k * AA + lane + 32], a1);
        }
        out[(size_t)e * AA + lane] = a0;
        if (lane < AA - 32) out[(size_t)e * AA + lane + 32] = a1;
        __syncwarp();
    }
}

// ---------------- launch ----------------
extern "C" void kernel_launch(void* const* d_in, const int* in_sizes, int n_in,
                              void* d_out, int out_size) {
    const float* x      = (const float*)d_in[0];
    const int*   eidx   = (const int*)  d_in[1];
    const float* eattr  = (const float*)d_in[2];
    const float* etime  = (const float*)d_in[3];
    const float* time_w = (const float*)d_in[4];
    const float* time_b = (const float*)d_in[5];
    const float* W_msg  = (const float*)d_in[6];
    const float* b_msg  = (const float*)d_in[7];
    const float* W_ih   = (const float*)d_in[8];
    const float* W_hh   = (const float*)d_in[9];
    const float* b_lstm = (const float*)d_in[10];
    const float* W_emb  = (const float*)d_in[11];
    const float* b_emb  = (const float*)d_in[12];
    const float* W_cls  = (const float*)d_in[13];
    const float* b_cls  = (const float*)d_in[14];
    float* out = (float*)d_out;

    cudaFuncSetAttribute(seq_kernel, cudaFuncAttributeMaxDynamicSharedMemorySize,
                         EE * (int)sizeof(int2));
    cudaFuncSetAttribute(scan_kernel, cudaFuncAttributeMaxDynamicSharedMemorySize,
                         SCAN_SMEM_F * (int)sizeof(float));

    misc_kernel<<<MISC_BLOCKS, 256>>>(eidx, W_emb, W_cls, b_emb, b_cls);
    seq_kernel<<<128, 256, EE * sizeof(int2)>>>(eidx);
    scan_kernel<<<SCAN_BLOCKS, 512, SCAN_SMEM_F * sizeof(float)>>>(
        W_msg, b_msg, W_ih, W_hh, b_lstm, time_w, time_b, eattr, etime);
    epilogue_kernel<<<256, 256>>>(x, eidx, out);
}

// round 7
// speedup vs baseline: 1.4007x; 1.0296x over previous
#include <cuda_runtime.h>
#include <math.h>

#define NN     200000
#define EE     8192
#define HH     64
#define TEDIM  32
#define EADIM  32
#define KF     192     // 2H + EA + TE
#define G4     256     // 4H
#define DFEAT  128
#define KZ     192     // H + D_FEAT
#define AA     50
#define SCAN_BLOCKS 148
#define NGROUP 16                         // one warp per group
#define NSTREAM (SCAN_BLOCKS * NGROUP)    // 2368 concurrent event streams

// misc kernel roles: [0,64) zero done + build pairs ; [64,104) fuse
#define MISC_ZERO_BLOCKS 64
#define MISC_FUSE_BLOCKS 40
#define MISC_BLOCKS (MISC_ZERO_BLOCKS + MISC_FUSE_BLOCKS)

// ---------------- device scratch (static, no runtime alloc) ----------------
__device__ float g_h[(size_t)NN * HH];     // node memory (not pre-zeroed: seq==0 => 0)
__device__ float g_c[(size_t)NN * HH];     // LSTM cell state
__device__ int   g_done[NN];               // per-node completed-endpoint counter
__device__ int2  g_pairs[EE];              // (src, dst)
__device__ int   g_seq[2 * EE];            // per-endpoint rank among same-node endpoints
__device__ float g_Wf[KZ * AA];            // fused W_emb @ W_cls
__device__ float g_bf[AA];                 // fused bias

// ---------------- helpers ----------------
__device__ __forceinline__ int ld_acq(const int* p) {
    int v;
    asm volatile("ld.global.acquire.gpu.b32 %0, [%1];" : "=r"(v) : "l"(p));
    return v;
}
__device__ __forceinline__ void st_rel(int* p, int v) {
    asm volatile("st.global.release.gpu.b32 [%0], %1;" :: "l"(p), "r"(v) : "memory");
}
__device__ __forceinline__ float sigf(float x) {
    return 1.f / (1.f + __expf(-x));
}

// ---------------- kernel 1: misc (zero done + pairs + fuse) — NO smem -----
__global__ void __launch_bounds__(256) misc_kernel(
    const int* __restrict__ eidx,
    const float* __restrict__ W_emb, const float* __restrict__ W_cls,
    const float* __restrict__ b_emb, const float* __restrict__ b_cls)
{
    int b = blockIdx.x;
    int t = threadIdx.x;
    if (b < MISC_ZERO_BLOCKS) {
        int n = b * 256 + t;              // endpoint id [0, 2*EE)
        int u = eidx[n];
        g_done[u] = 0;                    // racing same-value writes: benign
        if (n < EE) g_pairs[n] = make_int2(eidx[n], eidx[EE + n]);
    } else {
        int idx = (b - MISC_ZERO_BLOCKS) * 256 + t;
        if (idx < KZ * AA) {
            int k = idx / AA, a = idx % AA;
            float s = 0.f;
            #pragma unroll 8
            for (int c = 0; c < HH; c++) s = fmaf(W_emb[k * HH + c], W_cls[c * AA + a], s);
            g_Wf[idx] = s;
        } else if (idx < KZ * AA + AA) {
            int a = idx - KZ * AA;
            float s = b_cls[a];
            for (int c = 0; c < HH; c++) s = fmaf(b_emb[c], W_cls[c * AA + a], s);
            g_bf[a] = s;
        }
    }
}

// ---------------- kernel 2: per-endpoint sequence numbers (brute, smem) ----
__global__ void __launch_bounds__(256) seq_kernel(const int* __restrict__ eidx) {
    extern __shared__ int2 sp[];
    int t = threadIdx.x;
    for (int i = t; i < EE; i += 256)
        sp[i] = make_int2(eidx[i], eidx[EE + i]);
    __syncthreads();
    int lane = t & 31, w = t >> 5;
    for (int n = blockIdx.x * 8 + w; n < 2 * EE; n += gridDim.x * 8) {
        int e = n >> 1, s = n & 1;
        int2 pe = sp[e];
        int u = s ? pe.y : pe.x;
        int cnt = 0;
        for (int j = lane; j < e; j += 32) {
            int2 p = sp[j];
            cnt += (p.x == u) + (p.y == u);
        }
        #pragma unroll
        for (int off = 16; off > 0; off >>= 1)
            cnt += __shfl_down_sync(0xffffffffu, cnt, off);
        if (lane == 0) g_seq[n] = cnt;
    }
}

// ---------------- kernel 3: persistent dataflow scan, 16 warp-groups ------
// smem float offsets
#define O_WPM    0              // float2[64*64]: (w1+w2, w1-w2) per col
#define O_WC     8192           // float2[32*64]: comm weights, k-paired
#define O_WIH    12288          // permuted [k*64+col]*4+gate
#define O_WHH    28672
#define O_BMSG   45056
#define O_BLSTM  45120
#define O_TW     45376
#define O_TB     45408
#define O_GRP    45440          // per-group: 448 floats
#define GRP_F    448
#define SCAN_SMEM_F (O_GRP + NGROUP * GRP_F)   // 52608 floats = 205.5 KB

__global__ void __launch_bounds__(512, 1) scan_kernel(
    const float* __restrict__ Wmsg, const float* __restrict__ bmsg,
    const float* __restrict__ Wih,  const float* __restrict__ Whh,
    const float* __restrict__ blstm, const float* __restrict__ tw,
    const float* __restrict__ tb,   const float* __restrict__ eattr,
    const float* __restrict__ etime)
{
    extern __shared__ float sm[];
    float2* sWpm  = (float2*)(sm + O_WPM);
    float2* sWc   = (float2*)(sm + O_WC);
    float*  sWihP = sm + O_WIH;
    float*  sWhhP = sm + O_WHH;
    float*  sbmsg = sm + O_BMSG;
    float*  sblstm= sm + O_BLSTM;
    float*  stw   = sm + O_TW;
    float*  stb   = sm + O_TB;

    int t = threadIdx.x;
    int g = t >> 5, lt = t & 31;          // warp = group; thread owns cols lt, lt+32
    int ltB = lt + 32;

    float* grp = sm + O_GRP + g * GRP_F;
    float2* sHp   = (float2*)grp;            // [64] (hs, hd)
    float2* sSD   = (float2*)(grp + 128);    // [64] (hs+hd, hs-hd)
    float*  sComm = grp + 256;               // [64]
    float2* sMp   = (float2*)(grp + 320);    // [64] (m0, m1)

    // ---- load + transform weights (whole block) ----
    for (int i = t; i < 64 * 64; i += 512) {
        int k = i >> 6, col = i & 63;
        float w1 = Wmsg[k * HH + col];
        float w2 = Wmsg[(64 + k) * HH + col];
        sWpm[i] = make_float2(w1 + w2, w1 - w2);
    }
    for (int i = t; i < 32 * 64; i += 512) {
        int k2 = i >> 6, col = i & 63;
        sWc[i] = make_float2(Wmsg[(128 + 2 * k2) * HH + col],
                             Wmsg[(129 + 2 * k2) * HH + col]);
    }
    for (int i = t; i < HH * G4; i += 512) {
        int k = i >> 8, j = i & 255;
        int p = ((k << 6) + (j & 63)) * 4 + (j >> 6);
        sWihP[p] = Wih[i];
        sWhhP[p] = Whh[i];
    }
    if (t < HH)    sbmsg[t]  = bmsg[t];
    if (t < G4)    sblstm[t] = blstm[t];
    if (t < TEDIM) { stw[t] = tw[t]; stb[t] = tb[t]; }
    __syncthreads();

    for (int e = blockIdx.x * NGROUP + g; e < EE; e += NSTREAM) {
        int2 pr = g_pairs[e];
        int s0 = g_seq[2 * e], s1 = g_seq[2 * e + 1];
        bool w0 = (s0 > 0), w1 = (s1 > 0);

        if (w0 || w1) {      // dependency spin (bounded); skipped for first-touch
            int guard = 0;
            while (((w0 && ld_acq(&g_done[pr.x]) != s0) ||
                    (w1 && ld_acq(&g_done[pr.y]) != s1)) && ++guard < (1 << 18)) {}
        }

        // ---- state: 2 columns per thread; 0 if first touch this replay ----
        const float* hx = &g_h[(size_t)pr.x * HH];
        const float* hy = &g_h[(size_t)pr.y * HH];
        const float* cx = &g_c[(size_t)pr.x * HH];
        const float* cy = &g_c[(size_t)pr.y * HH];
        float hsA = w0 ? __ldcg(hx + lt)  : 0.f;
        float hsB = w0 ? __ldcg(hx + ltB) : 0.f;
        float csA = w0 ? __ldcg(cx + lt)  : 0.f;
        float csB = w0 ? __ldcg(cx + ltB) : 0.f;
        float hdA = w1 ? __ldcg(hy + lt)  : 0.f;
        float hdB = w1 ? __ldcg(hy + ltB) : 0.f;
        float cdA = w1 ? __ldcg(cy + lt)  : 0.f;
        float cdB = w1 ? __ldcg(cy + ltB) : 0.f;
        sHp[lt]  = make_float2(hsA, hdA);
        sHp[ltB] = make_float2(hsB, hdB);
        sSD[lt]  = make_float2(hsA + hdA, hsA - hdA);
        sSD[ltB] = make_float2(hsB + hdB, hsB - hdB);
        {
            sComm[lt] = eattr[e * EADIM + lt];                 // ea
            float tv = __ldg(&etime[e]);
            sComm[32 + lt] = cosf(tv * stw[lt] + stb[lt]);     // te
        }
        __syncwarp();

        // ---- gemm1 (sum/diff): thread -> cols lt, lt+32 ----
        float u0 = 0.f, v0 = 0.f, u1 = 0.f, v1 = 0.f;
        float ac0 = sbmsg[lt], ac1 = sbmsg[ltB];
        #pragma unroll 8
        for (int k = 0; k < 64; k++) {
            float2 sd = sSD[k];
            float2 wA = sWpm[k * 64 + lt];
            float2 wB = sWpm[k * 64 + ltB];
            u0 = fmaf(sd.x, wA.x, u0); v0 = fmaf(sd.y, wA.y, v0);
            u1 = fmaf(sd.x, wB.x, u1); v1 = fmaf(sd.y, wB.y, v1);
        }
        const float2* cm2 = (const float2*)sComm;
        #pragma unroll 8
        for (int k2 = 0; k2 < 32; k2++) {
            float2 c = cm2[k2];
            float2 wA = sWc[k2 * 64 + lt];
            float2 wB = sWc[k2 * 64 + ltB];
            ac0 = fmaf(c.x, wA.x, ac0); ac0 = fmaf(c.y, wA.y, ac0);
            ac1 = fmaf(c.x, wB.x, ac1); ac1 = fmaf(c.y, wB.y, ac1);
        }
        sMp[lt]  = make_float2(fmaxf(ac0 + 0.5f * (u0 - v0), 0.f),
                               fmaxf(ac0 + 0.5f * (u0 + v0), 0.f));
        sMp[ltB] = make_float2(fmaxf(ac1 + 0.5f * (u1 - v1), 0.f),
                               fmaxf(ac1 + 0.5f * (u1 + v1), 0.f));
        __syncwarp();

        // ---- gemm2: gates for cell cols lt (A) and lt+32 (B) ----
        float aA00 = sblstm[lt],        aA01 = sblstm[lt + 64];
        float aA02 = sblstm[lt + 128],  aA03 = sblstm[lt + 192];
        float aB00 = sblstm[ltB],       aB01 = sblstm[ltB + 64];
        float aB02 = sblstm[ltB + 128], aB03 = sblstm[ltB + 192];
        float aA10 = aA00, aA11 = aA01, aA12 = aA02, aA13 = aA03;
        float aB10 = aB00, aB11 = aB01, aB12 = aB02, aB13 = aB03;
        #pragma unroll 4
        for (int k = 0; k < 64; k++) {
            float2 m = sMp[k];
            float2 h = sHp[k];
            float4 wiA = *(const float4*)&sWihP[(k * 64 + lt) * 4];
            float4 whA = *(const float4*)&sWhhP[(k * 64 + lt) * 4];
            aA00 = fmaf(m.x, wiA.x, aA00); aA01 = fmaf(m.x, wiA.y, aA01);
            aA02 = fmaf(m.x, wiA.z, aA02); aA03 = fmaf(m.x, wiA.w, aA03);
            aA10 = fmaf(m.y, wiA.x, aA10); aA11 = fmaf(m.y, wiA.y, aA11);
            aA12 = fmaf(m.y, wiA.z, aA12); aA13 = fmaf(m.y, wiA.w, aA13);
            aA00 = fmaf(h.x, whA.x, aA00); aA01 = fmaf(h.x, whA.y, aA01);
            aA02 = fmaf(h.x, whA.z, aA02); aA03 = fmaf(h.x, whA.w, aA03);
            aA10 = fmaf(h.y, whA.x, aA10); aA11 = fmaf(h.y, whA.y, aA11);
            aA12 = fmaf(h.y, whA.z, aA12); aA13 = fmaf(h.y, whA.w, aA13);
            float4 wiB = *(const float4*)&sWihP[(k * 64 + ltB) * 4];
            float4 whB = *(const float4*)&sWhhP[(k * 64 + ltB) * 4];
            aB00 = fmaf(m.x, wiB.x, aB00); aB01 = fmaf(m.x, wiB.y, aB01);
            aB02 = fmaf(m.x, wiB.z, aB02); aB03 = fmaf(m.x, wiB.w, aB03);
            aB10 = fmaf(m.y, wiB.x, aB10); aB11 = fmaf(m.y, wiB.y, aB11);
            aB12 = fmaf(m.y, wiB.z, aB12); aB13 = fmaf(m.y, wiB.w, aB13);
            aB00 = fmaf(h.x, whB.x, aB00); aB01 = fmaf(h.x, whB.y, aB01);
            aB02 = fmaf(h.x, whB.z, aB02); aB03 = fmaf(h.x, whB.w, aB03);
            aB10 = fmaf(h.y, whB.x, aB10); aB11 = fmaf(h.y, whB.y, aB11);
            aB12 = fmaf(h.y, whB.z, aB12); aB13 = fmaf(h.y, whB.w, aB13);
        }

        // ---- LSTM elementwise + state write (dst row wins on self-loop) ----
        bool selfloop = (pr.x == pr.y);
        float* hyw = &g_h[(size_t)pr.y * HH];
        float* cyw = &g_c[(size_t)pr.y * HH];
        {   // row 1 (dst)
            float cnA = sigf(aA11) * cdA + sigf(aA10) * tanhf(aA12);
            float hnA = sigf(aA13) * tanhf(cnA);
            float cnB = sigf(aB11) * cdB + sigf(aB10) * tanhf(aB12);
            float hnB = sigf(aB13) * tanhf(cnB);
            __stcg(hyw + lt, hnA);  __stcg(cyw + lt, cnA);
            __stcg(hyw + ltB, hnB); __stcg(cyw + ltB, cnB);
        }
        if (!selfloop) {  // row 0 (src)
            float* hxw = &g_h[(size_t)pr.x * HH];
            float* cxw = &g_c[(size_t)pr.x * HH];
            float cnA = sigf(aA01) * csA + sigf(aA00) * tanhf(aA02);
            float hnA = sigf(aA03) * tanhf(cnA);
            float cnB = sigf(aB01) * csB + sigf(aB00) * tanhf(aB02);
            float hnB = sigf(aB03) * tanhf(cnB);
            __stcg(hxw + lt, hnA);  __stcg(cxw + lt, cnA);
            __stcg(hxw + ltB, hnB); __stcg(cxw + ltB, cnB);
        }
        __syncwarp();

        if (lt == 0) {
            __threadfence();
            if (selfloop) {
                st_rel(&g_done[pr.x], s0 + 2);
            } else {
                st_rel(&g_done[pr.x], s0 + 1);
                st_rel(&g_done[pr.y], s1 + 1);
            }
        }
        __syncwarp();
    }
}

// ---------------- kernel 4: epilogue, 2-event ILP, dynamic smem -----------
// dyn smem layout (floats): sWf[KZ*AA] | sbf[AA padded to 64] | sCat[8][2][KZ]
#define EP_O_WF   0
#define EP_O_BF   (KZ * AA)                 // 9600
#define EP_O_CAT  (EP_O_BF + 64)            // 9664
#define EP_SMEM_F (EP_O_CAT + 8 * 2 * KZ)   // 12736 floats = 50944 B

__global__ void __launch_bounds__(256) epilogue_kernel(const float* __restrict__ x,
                                                       const int* __restrict__ eidx,
                                                       float* __restrict__ out) {
    extern __shared__ float esm[];
    float* sWf = esm + EP_O_WF;
    float* sbf = esm + EP_O_BF;
    int t = threadIdx.x;
    for (int i = t; i < KZ * AA; i += 256) sWf[i] = g_Wf[i];
    if (t < AA) sbf[t] = g_bf[t];
    __syncthreads();
    int lane = t & 31, w = t >> 5;
    float* s0 = esm + EP_O_CAT + w * 2 * KZ;
    float* s1 = s0 + KZ;
    int base = (blockIdx.x * 8 + w) * 4;            // 4 events per warp, 2 pairs
    #pragma unroll
    for (int pass = 0; pass < 2; pass++) {
        int e0 = base + pass * 2, e1 = e0 + 1;
        int d0 = eidx[EE + e0], d1 = eidx[EE + e1];
        const float* h0 = &g_h[(size_t)d0 * HH];
        const float* h1 = &g_h[(size_t)d1 * HH];
        const float* x0 = &x[(size_t)d0 * DFEAT];
        const float* x1 = &x[(size_t)d1 * DFEAT];
        #pragma unroll
        for (int q = 0; q < 6; q++) {
            int k = lane + q * 32;
            s0[k] = (k < HH) ? h0[k] : x0[k - HH];
            s1[k] = (k < HH) ? h1[k] : x1[k - HH];
        }
        __syncwarp();
        bool hi = (lane < AA - 32);
        float a00 = sbf[lane], a01 = hi ? sbf[lane + 32] : 0.f;
        float a10 = a00, a11 = a01;
        #pragma unroll 4
        for (int k = 0; k < KZ; k++) {
            float v0 = s0[k], v1 = s1[k];
            float wA = sWf[k * AA + lane];
            a00 = fmaf(v0, wA, a00);
            a10 = fmaf(v1, wA, a10);
            if (hi) {
                float wB = sWf[k * AA + lane + 32];
                a01 = fmaf(v0, wB, a01);
                a11 = fmaf(v1, wB, a11);
            }
        }
        out[(size_t)e0 * AA + lane] = a00;
        out[(size_t)e1 * AA + lane] = a10;
        if (hi) {
            out[(size_t)e0 * AA + lane + 32] = a01;
            out[(size_t)e1 * AA + lane + 32] = a11;
        }
        __syncwarp();
    }
}

// ---------------- launch ----------------
extern "C" void kernel_launch(void* const* d_in, const int* in_sizes, int n_in,
                              void* d_out, int out_size) {
    const float* x      = (const float*)d_in[0];
    const int*   eidx   = (const int*)  d_in[1];
    const float* eattr  = (const float*)d_in[2];
    const float* etime  = (const float*)d_in[3];
    const float* time_w = (const float*)d_in[4];
    const float* time_b = (const float*)d_in[5];
    const float* W_msg  = (const float*)d_in[6];
    const float* b_msg  = (const float*)d_in[7];
    const float* W_ih   = (const float*)d_in[8];
    const float* W_hh   = (const float*)d_in[9];
    const float* b_lstm = (const float*)d_in[10];
    const float* W_emb  = (const float*)d_in[11];
    const float* b_emb  = (const float*)d_in[12];
    const float* W_cls  = (const float*)d_in[13];
    const float* b_cls  = (const float*)d_in[14];
    float* out = (float*)d_out;

    cudaFuncSetAttribute(seq_kernel, cudaFuncAttributeMaxDynamicSharedMemorySize,
                         EE * (int)sizeof(int2));
    cudaFuncSetAttribute(scan_kernel, cudaFuncAttributeMaxDynamicSharedMemorySize,
                         SCAN_SMEM_F * (int)sizeof(float));
    cudaFuncSetAttribute(epilogue_kernel, cudaFuncAttributeMaxDynamicSharedMemorySize,
                         EP_SMEM_F * (int)sizeof(float));

    misc_kernel<<<MISC_BLOCKS, 256>>>(eidx, W_emb, W_cls, b_emb, b_cls);
    seq_kernel<<<128, 256, EE * sizeof(int2)>>>(eidx);
    scan_kernel<<<SCAN_BLOCKS, 512, SCAN_SMEM_F * sizeof(float)>>>(
        W_msg, b_msg, W_ih, W_hh, b_lstm, time_w, time_b, eattr, etime);
    epilogue_kernel<<<256, 256, EP_SMEM_F * sizeof(float)>>>(x, eidx, out);
}

// round 8
// speedup vs baseline: 1.5916x; 1.1363x over previous
#include <cuda_runtime.h>
#include <math.h>

#define NN     200000
#define EE     8192
#define HH     64
#define TEDIM  32
#define EADIM  32
#define G4     256     // 4H
#define DFEAT  128
#define KZ     192     // H + D_FEAT
#define AA     50
#define SCAN_BLOCKS 148
#define NGROUP 8                          // 64-thread groups
#define NSTREAM (SCAN_BLOCKS * NGROUP)    // 1184 pair streams

// misc kernel roles: [0,64) zero done + build pairs ; [64,104) fuse
#define MISC_ZERO_BLOCKS 64
#define MISC_FUSE_BLOCKS 40
#define MISC_BLOCKS (MISC_ZERO_BLOCKS + MISC_FUSE_BLOCKS)

// ---------------- device scratch (static, no runtime alloc) ----------------
__device__ float g_h[(size_t)NN * HH];     // node memory (not pre-zeroed: seq==0 => 0)
__device__ float g_c[(size_t)NN * HH];     // LSTM cell state
__device__ int   g_done[NN];               // per-node completed-endpoint counter
__device__ int2  g_pairs[EE];              // (src, dst)
__device__ int   g_seq[2 * EE];            // per-endpoint rank among same-node endpoints
__device__ float g_Wf[KZ * AA];            // fused W_emb @ W_cls
__device__ float g_bf[AA];                 // fused bias

// ---------------- helpers ----------------
__device__ __forceinline__ int ld_acq(const int* p) {
    int v;
    asm volatile("ld.global.acquire.gpu.b32 %0, [%1];" : "=r"(v) : "l"(p));
    return v;
}
__device__ __forceinline__ void st_rel(int* p, int v) {
    asm volatile("st.global.release.gpu.b32 [%0], %1;" :: "l"(p), "r"(v) : "memory");
}
__device__ __forceinline__ void bar_group(int g) {
    asm volatile("bar.sync %0, 64;" :: "r"(g + 1) : "memory");
}
__device__ __forceinline__ float sigf(float x) {
    return 1.f / (1.f + __expf(-x));
}

// ---------------- kernel 1: misc (zero done + pairs + fuse) — NO smem -----
__global__ void __launch_bounds__(256) misc_kernel(
    const int* __restrict__ eidx,
    const float* __restrict__ W_emb, const float* __restrict__ W_cls,
    const float* __restrict__ b_emb, const float* __restrict__ b_cls)
{
    int b = blockIdx.x;
    int t = threadIdx.x;
    if (b < MISC_ZERO_BLOCKS) {
        int n = b * 256 + t;              // endpoint id [0, 2*EE)
        int u = eidx[n];
        g_done[u] = 0;                    // racing same-value writes: benign
        if (n < EE) g_pairs[n] = make_int2(eidx[n], eidx[EE + n]);
    } else {
        int idx = (b - MISC_ZERO_BLOCKS) * 256 + t;
        if (idx < KZ * AA) {
            int k = idx / AA, a = idx % AA;
            float s = 0.f;
            #pragma unroll 8
            for (int c = 0; c < HH; c++) s = fmaf(W_emb[k * HH + c], W_cls[c * AA + a], s);
            g_Wf[idx] = s;
        } else if (idx < KZ * AA + AA) {
            int a = idx - KZ * AA;
            float s = b_cls[a];
            for (int c = 0; c < HH; c++) s = fmaf(b_emb[c], W_cls[c * AA + a], s);
            g_bf[a] = s;
        }
    }
}

// ---------------- kernel 2: seq — both endpoints of an event in one pass ---
__global__ void __launch_bounds__(256) seq_kernel(const int* __restrict__ eidx) {
    extern __shared__ int2 sp[];
    int t = threadIdx.x;
    for (int i = t; i < EE; i += 256)
        sp[i] = make_int2(eidx[i], eidx[EE + i]);
    __syncthreads();
    int lane = t & 31, w = t >> 5;
    for (int e = blockIdx.x * 8 + w; e < EE; e += gridDim.x * 8) {
        int2 pe = sp[e];
        int u0 = pe.x, u1 = pe.y;
        int c0 = 0, c1 = 0;
        for (int j = lane; j < e; j += 32) {
            int2 p = sp[j];
            c0 += (p.x == u0) + (p.y == u0);
            c1 += (p.x == u1) + (p.y == u1);
        }
        #pragma unroll
        for (int off = 16; off > 0; off >>= 1) {
            c0 += __shfl_down_sync(0xffffffffu, c0, off);
            c1 += __shfl_down_sync(0xffffffffu, c1, off);
        }
        if (lane == 0) {
            g_seq[2 * e] = c0;
            g_seq[2 * e + 1] = c1;
        }
    }
}

// ---------------- kernel 3: scan — pair-of-events per 64-thread group -----
// smem float offsets
#define O_WPM    0              // float2[64*64]: (w1+w2, w1-w2) per col
#define O_WC     8192           // float2[32*64]: comm weights, k-paired
#define O_WIH    12288          // permuted [k*64+col]*4+gate
#define O_WHH    28672
#define O_BMSG   45056
#define O_BLSTM  45120
#define O_TW     45376
#define O_TB     45408
#define O_GRP    45440
// group layout: HpA(128) HpB(128) SDA(128) SDB(128) CommA(64) CommB(64) MpA(128) MpB(128)
#define GRP_F    896
#define SCAN_SMEM_F (O_GRP + NGROUP * GRP_F)   // 52608 floats = 205.5 KB

struct ScanCtx {
    const float2* sWpm;
    const float2* sWc;
    const float*  sWihP;
    const float*  sWhhP;
    const float*  sbmsg;
    const float*  sblstm;
    const float*  stw;
    const float*  stb;
    const float*  eattr;
    const float*  etime;
};

// single-event path (used only for rare conflicting pairs)
__device__ __forceinline__ void process_one(
    int e, int lt, int g,
    float2* sHp, float2* sSD, float* sComm, float2* sMp, const ScanCtx& cx)
{
    int2 pr = g_pairs[e];
    int s0 = g_seq[2 * e], s1 = g_seq[2 * e + 1];
    bool w0 = (s0 > 0), w1 = (s1 > 0);
    if (w0 || w1) {
        int guard = 0;
        while (((w0 && ld_acq(&g_done[pr.x]) != s0) ||
                (w1 && ld_acq(&g_done[pr.y]) != s1)) && ++guard < (1 << 18)) {}
    }
    float hs = w0 ? __ldcg(&g_h[(size_t)pr.x * HH + lt]) : 0.f;
    float cs = w0 ? __ldcg(&g_c[(size_t)pr.x * HH + lt]) : 0.f;
    float hd = w1 ? __ldcg(&g_h[(size_t)pr.y * HH + lt]) : 0.f;
    float cd = w1 ? __ldcg(&g_c[(size_t)pr.y * HH + lt]) : 0.f;
    sHp[lt] = make_float2(hs, hd);
    sSD[lt] = make_float2(hs + hd, hs - hd);
    sComm[lt] = (lt < EADIM) ? cx.eattr[e * EADIM + lt]
              : cosf(__ldg(&cx.etime[e]) * cx.stw[lt - EADIM] + cx.stb[lt - EADIM]);
    bar_group(g);

    float u = 0.f, v = 0.f, ac = cx.sbmsg[lt];
    #pragma unroll 8
    for (int k = 0; k < 64; k++) {
        float2 sd = sSD[k];
        float2 w  = cx.sWpm[k * 64 + lt];
        u = fmaf(sd.x, w.x, u);
        v = fmaf(sd.y, w.y, v);
    }
    const float2* cm2 = (const float2*)sComm;
    #pragma unroll 8
    for (int k2 = 0; k2 < 32; k2++) {
        float2 c = cm2[k2];
        float2 w = cx.sWc[k2 * 64 + lt];
        ac = fmaf(c.x, w.x, ac);
        ac = fmaf(c.y, w.y, ac);
    }
    sMp[lt] = make_float2(fmaxf(ac + 0.5f * (u - v), 0.f),
                          fmaxf(ac + 0.5f * (u + v), 0.f));
    bar_group(g);

    float a00 = cx.sblstm[lt],       a01 = cx.sblstm[lt + 64];
    float a02 = cx.sblstm[lt + 128], a03 = cx.sblstm[lt + 192];
    float a10 = a00, a11 = a01, a12 = a02, a13 = a03;
    #pragma unroll 8
    for (int k = 0; k < 64; k++) {
        float2 m = sMp[k];
        float2 h = sHp[k];
        float4 wi = *(const float4*)&cx.sWihP[(k * 64 + lt) * 4];
        float4 wh = *(const float4*)&cx.sWhhP[(k * 64 + lt) * 4];
        a00 = fmaf(m.x, wi.x, a00); a01 = fmaf(m.x, wi.y, a01);
        a02 = fmaf(m.x, wi.z, a02); a03 = fmaf(m.x, wi.w, a03);
        a10 = fmaf(m.y, wi.x, a10); a11 = fmaf(m.y, wi.y, a11);
        a12 = fmaf(m.y, wi.z, a12); a13 = fmaf(m.y, wi.w, a13);
        a00 = fmaf(h.x, wh.x, a00); a01 = fmaf(h.x, wh.y, a01);
        a02 = fmaf(h.x, wh.z, a02); a03 = fmaf(h.x, wh.w, a03);
        a10 = fmaf(h.y, wh.x, a10); a11 = fmaf(h.y, wh.y, a11);
        a12 = fmaf(h.y, wh.z, a12); a13 = fmaf(h.y, wh.w, a13);
    }
    bool selfloop = (pr.x == pr.y);
    {
        float cn = sigf(a11) * cd + sigf(a10) * tanhf(a12);
        float hn = sigf(a13) * tanhf(cn);
        __stcg(&g_h[(size_t)pr.y * HH + lt], hn);
        __stcg(&g_c[(size_t)pr.y * HH + lt], cn);
    }
    if (!selfloop) {
        float cn = sigf(a01) * cs + sigf(a00) * tanhf(a02);
        float hn = sigf(a03) * tanhf(cn);
        __stcg(&g_h[(size_t)pr.x * HH + lt], hn);
        __stcg(&g_c[(size_t)pr.x * HH + lt], cn);
    }
    bar_group(g);
    if (lt == 0) {
        __threadfence();
        if (selfloop) {
            st_rel(&g_done[pr.x], s0 + 2);
        } else {
            st_rel(&g_done[pr.x], s0 + 1);
            st_rel(&g_done[pr.y], s1 + 1);
        }
    }
    bar_group(g);
}

__global__ void __launch_bounds__(512, 1) scan_kernel(
    const float* __restrict__ Wmsg, const float* __restrict__ bmsg,
    const float* __restrict__ Wih,  const float* __restrict__ Whh,
    const float* __restrict__ blstm, const float* __restrict__ tw,
    const float* __restrict__ tb,   const float* __restrict__ eattr,
    const float* __restrict__ etime)
{
    extern __shared__ float sm[];
    int t = threadIdx.x;
    int g = t >> 6, lt = t & 63;

    ScanCtx cx;
    cx.sWpm  = (const float2*)(sm + O_WPM);
    cx.sWc   = (const float2*)(sm + O_WC);
    cx.sWihP = sm + O_WIH;
    cx.sWhhP = sm + O_WHH;
    cx.sbmsg = sm + O_BMSG;
    cx.sblstm= sm + O_BLSTM;
    cx.stw   = sm + O_TW;
    cx.stb   = sm + O_TB;
    cx.eattr = eattr;
    cx.etime = etime;

    float* grp = sm + O_GRP + g * GRP_F;
    float2* sHpA   = (float2*)grp;
    float2* sHpB   = (float2*)(grp + 128);
    float2* sSDA   = (float2*)(grp + 256);
    float2* sSDB   = (float2*)(grp + 384);
    float*  sCommA = grp + 512;
    float*  sCommB = grp + 576;
    float2* sMpA   = (float2*)(grp + 640);
    float2* sMpB   = (float2*)(grp + 768);

    // ---- load + transform weights (whole block) ----
    {
        float2* wWpm = (float2*)(sm + O_WPM);
        float2* wWc  = (float2*)(sm + O_WC);
        float*  wIh  = sm + O_WIH;
        float*  wHh  = sm + O_WHH;
        for (int i = t; i < 64 * 64; i += 512) {
            int k = i >> 6, col = i & 63;
            float w1 = Wmsg[k * HH + col];
            float w2 = Wmsg[(64 + k) * HH + col];
            wWpm[i] = make_float2(w1 + w2, w1 - w2);
        }
        for (int i = t; i < 32 * 64; i += 512) {
            int k2 = i >> 6, col = i & 63;
            wWc[i] = make_float2(Wmsg[(128 + 2 * k2) * HH + col],
                                 Wmsg[(129 + 2 * k2) * HH + col]);
        }
        for (int i = t; i < HH * G4; i += 512) {
            int k = i >> 8, j = i & 255;
            int p = ((k << 6) + (j & 63)) * 4 + (j >> 6);
            wIh[p] = Wih[i];
            wHh[p] = Whh[i];
        }
        if (t < HH)    (sm + O_BMSG)[t]  = bmsg[t];
        if (t < G4)    (sm + O_BLSTM)[t] = blstm[t];
        if (t < TEDIM) { (sm + O_TW)[t] = tw[t]; (sm + O_TB)[t] = tb[t]; }
    }
    __syncthreads();

    for (int p = blockIdx.x * NGROUP + g; p < EE / 2; p += NSTREAM) {
        int eA = 2 * p, eB = 2 * p + 1;
        int2 prA = g_pairs[eA], prB = g_pairs[eB];

        bool conflict = (prA.x == prB.x) | (prA.x == prB.y) |
                        (prA.y == prB.x) | (prA.y == prB.y);
        if (conflict) {    // rare: process sequentially
            process_one(eA, lt, g, sHpA, sSDA, sCommA, sMpA, cx);
            process_one(eB, lt, g, sHpA, sSDA, sCommA, sMpA, cx);
            continue;
        }

        int s0A = g_seq[2 * eA], s1A = g_seq[2 * eA + 1];
        int s0B = g_seq[2 * eB], s1B = g_seq[2 * eB + 1];
        bool wA0 = (s0A > 0), wA1 = (s1A > 0), wB0 = (s0B > 0), wB1 = (s1B > 0);
        if (wA0 | wA1 | wB0 | wB1) {
            int guard = 0;
            while (((wA0 && ld_acq(&g_done[prA.x]) != s0A) ||
                    (wA1 && ld_acq(&g_done[prA.y]) != s1A) ||
                    (wB0 && ld_acq(&g_done[prB.x]) != s0B) ||
                    (wB1 && ld_acq(&g_done[prB.y]) != s1B)) && ++guard < (1 << 18)) {}
        }

        // ---- states + comm for both events ----
        float hsA = wA0 ? __ldcg(&g_h[(size_t)prA.x * HH + lt]) : 0.f;
        float csA = wA0 ? __ldcg(&g_c[(size_t)prA.x * HH + lt]) : 0.f;
        float hdA = wA1 ? __ldcg(&g_h[(size_t)prA.y * HH + lt]) : 0.f;
        float cdA = wA1 ? __ldcg(&g_c[(size_t)prA.y * HH + lt]) : 0.f;
        float hsB = wB0 ? __ldcg(&g_h[(size_t)prB.x * HH + lt]) : 0.f;
        float csB = wB0 ? __ldcg(&g_c[(size_t)prB.x * HH + lt]) : 0.f;
        float hdB = wB1 ? __ldcg(&g_h[(size_t)prB.y * HH + lt]) : 0.f;
        float cdB = wB1 ? __ldcg(&g_c[(size_t)prB.y * HH + lt]) : 0.f;
        sHpA[lt] = make_float2(hsA, hdA);
        sSDA[lt] = make_float2(hsA + hdA, hsA - hdA);
        sHpB[lt] = make_float2(hsB, hdB);
        sSDB[lt] = make_float2(hsB + hdB, hsB - hdB);
        if (lt < EADIM) {
            sCommA[lt] = eattr[eA * EADIM + lt];
            sCommB[lt] = eattr[eB * EADIM + lt];
        } else {
            int i = lt - EADIM;
            sCommA[lt] = cosf(__ldg(&etime[eA]) * cx.stw[i] + cx.stb[i]);
            sCommB[lt] = cosf(__ldg(&etime[eB]) * cx.stw[i] + cx.stb[i]);
        }
        bar_group(g);

        // ---- gemm1 for both events, weights loaded once ----
        float uA = 0.f, vA = 0.f, uB = 0.f, vB = 0.f;
        float acA = cx.sbmsg[lt], acB = acA;
        #pragma unroll 8
        for (int k = 0; k < 64; k++) {
            float2 w  = cx.sWpm[k * 64 + lt];
            float2 a = sSDA[k];
            float2 b = sSDB[k];
            uA = fmaf(a.x, w.x, uA); vA = fmaf(a.y, w.y, vA);
            uB = fmaf(b.x, w.x, uB); vB = fmaf(b.y, w.y, vB);
        }
        const float2* cmA = (const float2*)sCommA;
        const float2* cmB = (const float2*)sCommB;
        #pragma unroll 8
        for (int k2 = 0; k2 < 32; k2++) {
            float2 w = cx.sWc[k2 * 64 + lt];
            float2 a = cmA[k2];
            float2 b = cmB[k2];
            acA = fmaf(a.x, w.x, acA); acA = fmaf(a.y, w.y, acA);
            acB = fmaf(b.x, w.x, acB); acB = fmaf(b.y, w.y, acB);
        }
        sMpA[lt] = make_float2(fmaxf(acA + 0.5f * (uA - vA), 0.f),
                               fmaxf(acA + 0.5f * (uA + vA), 0.f));
        sMpB[lt] = make_float2(fmaxf(acB + 0.5f * (uB - vB), 0.f),
                               fmaxf(acB + 0.5f * (uB + vB), 0.f));
        bar_group(g);

        // ---- gemm2 for both events, weights loaded once (16 accumulators) ----
        float bl0 = cx.sblstm[lt],       bl1 = cx.sblstm[lt + 64];
        float bl2 = cx.sblstm[lt + 128], bl3 = cx.sblstm[lt + 192];
        float aA00 = bl0, aA01 = bl1, aA02 = bl2, aA03 = bl3;
        float aA10 = bl0, aA11 = bl1, aA12 = bl2, aA13 = bl3;
        float aB00 = bl0, aB01 = bl1, aB02 = bl2, aB03 = bl3;
        float aB10 = bl0, aB11 = bl1, aB12 = bl2, aB13 = bl3;
        #pragma unroll 4
        for (int k = 0; k < 64; k++) {
            float4 wi = *(const float4*)&cx.sWihP[(k * 64 + lt) * 4];
            float4 wh = *(const float4*)&cx.sWhhP[(k * 64 + lt) * 4];
            float2 mA = sMpA[k]; float2 hA = sHpA[k];
            float2 mB = sMpB[k]; float2 hB = sHpB[k];
            aA00 = fmaf(mA.x, wi.x, aA00); aA01 = fmaf(mA.x, wi.y, aA01);
            aA02 = fmaf(mA.x, wi.z, aA02); aA03 = fmaf(mA.x, wi.w, aA03);
            aA10 = fmaf(mA.y, wi.x, aA10); aA11 = fmaf(mA.y, wi.y, aA11);
            aA12 = fmaf(mA.y, wi.z, aA12); aA13 = fmaf(mA.y, wi.w, aA13);
            aA00 = fmaf(hA.x, wh.x, aA00); aA01 = fmaf(hA.x, wh.y, aA01);
            aA02 = fmaf(hA.x, wh.z, aA02); aA03 = fmaf(hA.x, wh.w, aA03);
            aA10 = fmaf(hA.y, wh.x, aA10); aA11 = fmaf(hA.y, wh.y, aA11);
            aA12 = fmaf(hA.y, wh.z, aA12); aA13 = fmaf(hA.y, wh.w, aA13);
            aB00 = fmaf(mB.x, wi.x, aB00); aB01 = fmaf(mB.x, wi.y, aB01);
            aB02 = fmaf(mB.x, wi.z, aB02); aB03 = fmaf(mB.x, wi.w, aB03);
            aB10 = fmaf(mB.y, wi.x, aB10); aB11 = fmaf(mB.y, wi.y, aB11);
            aB12 = fmaf(mB.y, wi.z, aB12); aB13 = fmaf(mB.y, wi.w, aB13);
            aB00 = fmaf(hB.x, wh.x, aB00); aB01 = fmaf(hB.x, wh.y, aB01);
            aB02 = fmaf(hB.x, wh.z, aB02); aB03 = fmaf(hB.x, wh.w, aB03);
            aB10 = fmaf(hB.y, wh.x, aB10); aB11 = fmaf(hB.y, wh.y, aB11);
            aB12 = fmaf(hB.y, wh.z, aB12); aB13 = fmaf(hB.y, wh.w, aB13);
        }

        // ---- elementwise + stores (dst row wins on per-event self-loop) ----
        bool slA = (prA.x == prA.y), slB = (prB.x == prB.y);
        {
            float cn = sigf(aA11) * cdA + sigf(aA10) * tanhf(aA12);
            float hn = sigf(aA13) * tanhf(cn);
            __stcg(&g_h[(size_t)prA.y * HH + lt], hn);
            __stcg(&g_c[(size_t)prA.y * HH + lt], cn);
        }
        if (!slA) {
            float cn = sigf(aA01) * csA + sigf(aA00) * tanhf(aA02);
            float hn = sigf(aA03) * tanhf(cn);
            __stcg(&g_h[(size_t)prA.x * HH + lt], hn);
            __stcg(&g_c[(size_t)prA.x * HH + lt], cn);
        }
        {
            float cn = sigf(aB11) * cdB + sigf(aB10) * tanhf(aB12);
            float hn = sigf(aB13) * tanhf(cn);
            __stcg(&g_h[(size_t)prB.y * HH + lt], hn);
            __stcg(&g_c[(size_t)prB.y * HH + lt], cn);
        }
        if (!slB) {
            float cn = sigf(aB01) * csB + sigf(aB00) * tanhf(aB02);
            float hn = sigf(aB03) * tanhf(cn);
            __stcg(&g_h[(size_t)prB.x * HH + lt], hn);
            __stcg(&g_c[(size_t)prB.x * HH + lt], cn);
        }
        bar_group(g);

        if (lt == 0) {
            __threadfence();
            if (slA) st_rel(&g_done[prA.x], s0A + 2);
            else { st_rel(&g_done[prA.x], s0A + 1); st_rel(&g_done[prA.y], s1A + 1); }
            if (slB) st_rel(&g_done[prB.x], s0B + 2);
            else { st_rel(&g_done[prB.x], s0B + 1); st_rel(&g_done[prB.y], s1B + 1); }
        }
        bar_group(g);
    }
}

// ---------------- kernel 4: epilogue, 2-event ILP, 512 blocks --------------
// dyn smem layout (floats): sWf[KZ*AA] | sbf[64] | sCat[8][2][KZ]
#define EP_O_WF   0
#define EP_O_BF   (KZ * AA)                 // 9600
#define EP_O_CAT  (EP_O_BF + 64)            // 9664
#define EP_SMEM_F (EP_O_CAT + 8 * 2 * KZ)   // 12736 floats

__global__ void __launch_bounds__(256) epilogue_kernel(const float* __restrict__ x,
                                                       const int* __restrict__ eidx,
                                                       float* __restrict__ out) {
    extern __shared__ float esm[];
    float* sWf = esm + EP_O_WF;
    float* sbf = esm + EP_O_BF;
    int t = threadIdx.x;
    for (int i = t; i < KZ * AA; i += 256) sWf[i] = g_Wf[i];
    if (t < AA) sbf[t] = g_bf[t];
    __syncthreads();
    int lane = t & 31, w = t >> 5;
    float* s0 = esm + EP_O_CAT + w * 2 * KZ;
    float* s1 = s0 + KZ;
    int e0 = (blockIdx.x * 8 + w) * 2, e1 = e0 + 1;   // 2 events per warp
    int d0 = eidx[EE + e0], d1 = eidx[EE + e1];
    const float* h0 = &g_h[(size_t)d0 * HH];
    const float* h1 = &g_h[(size_t)d1 * HH];
    const float* x0 = &x[(size_t)d0 * DFEAT];
    const float* x1 = &x[(size_t)d1 * DFEAT];
    #pragma unroll
    for (int q = 0; q < 6; q++) {
        int k = lane + q * 32;
        s0[k] = (k < HH) ? h0[k] : x0[k - HH];
        s1[k] = (k < HH) ? h1[k] : x1[k - HH];
    }
    __syncwarp();
    bool hi = (lane < AA - 32);
    float a00 = sbf[lane], a01 = hi ? sbf[lane + 32] : 0.f;
    float a10 = a00, a11 = a01;
    #pragma unroll 4
    for (int k = 0; k < KZ; k++) {
        float v0 = s0[k], v1 = s1[k];
        float wA = sWf[k * AA + lane];
        a00 = fmaf(v0, wA, a00);
        a10 = fmaf(v1, wA, a10);
        if (hi) {
            float wB = sWf[k * AA + lane + 32];
            a01 = fmaf(v0, wB, a01);
            a11 = fmaf(v1, wB, a11);
        }
    }
    out[(size_t)e0 * AA + lane] = a00;
    out[(size_t)e1 * AA + lane] = a10;
    if (hi) {
        out[(size_t)e0 * AA + lane + 32] = a01;
        out[(size_t)e1 * AA + lane + 32] = a11;
    }
}

// ---------------- launch ----------------
extern "C" void kernel_launch(void* const* d_in, const int* in_sizes, int n_in,
                              void* d_out, int out_size) {
    const float* x      = (const float*)d_in[0];
    const int*   eidx   = (const int*)  d_in[1];
    const float* eattr  = (const float*)d_in[2];
    const float* etime  = (const float*)d_in[3];
    const float* time_w = (const float*)d_in[4];
    const float* time_b = (const float*)d_in[5];
    const float* W_msg  = (const float*)d_in[6];
    const float* b_msg  = (const float*)d_in[7];
    const float* W_ih   = (const float*)d_in[8];
    const float* W_hh   = (const float*)d_in[9];
    const float* b_lstm = (const float*)d_in[10];
    const float* W_emb  = (const float*)d_in[11];
    const float* b_emb  = (const float*)d_in[12];
    const float* W_cls  = (const float*)d_in[13];
    const float* b_cls  = (const float*)d_in[14];
    float* out = (float*)d_out;

    cudaFuncSetAttribute(seq_kernel, cudaFuncAttributeMaxDynamicSharedMemorySize,
                         EE * (int)sizeof(int2));
    cudaFuncSetAttribute(scan_kernel, cudaFuncAttributeMaxDynamicSharedMemorySize,
                         SCAN_SMEM_F * (int)sizeof(float));
    cudaFuncSetAttribute(epilogue_kernel, cudaFuncAttributeMaxDynamicSharedMemorySize,
                         EP_SMEM_F * (int)sizeof(float));

    misc_kernel<<<MISC_BLOCKS, 256>>>(eidx, W_emb, W_cls, b_emb, b_cls);
    seq_kernel<<<128, 256, EE * sizeof(int2)>>>(eidx);
    scan_kernel<<<SCAN_BLOCKS, 512, SCAN_SMEM_F * sizeof(float)>>>(
        W_msg, b_msg, W_ih, W_hh, b_lstm, time_w, time_b, eattr, etime);
    epilogue_kernel<<<512, 256, EP_SMEM_F * sizeof(float)>>>(x, eidx, out);
}

// round 9
// speedup vs baseline: 1.7893x; 1.1242x over previous
#include <cuda_runtime.h>
#include <math.h>

#define NN     200000
#define EE     8192
#define HH     64
#define TEDIM  32
#define EADIM  32
#define G4     256     // 4H
#define DFEAT  128
#define KZ     192     // H + D_FEAT
#define AA     50
#define SCAN_BLOCKS 148
#define BDIM   640                        // 20 warps
#define NGROUP 10                         // 64-thread groups
#define NSTREAM (SCAN_BLOCKS * NGROUP)    // 1480 pair streams

// misc kernel roles: [0,64) zero done + build pairs ; [64,104) fuse
#define MISC_ZERO_BLOCKS 64
#define MISC_FUSE_BLOCKS 40
#define MISC_BLOCKS (MISC_ZERO_BLOCKS + MISC_FUSE_BLOCKS)

// ---------------- device scratch (static, no runtime alloc) ----------------
__device__ float g_h[(size_t)NN * HH];     // node memory (not pre-zeroed: seq==0 => 0)
__device__ float g_c[(size_t)NN * HH];     // LSTM cell state
__device__ int   g_done[NN];               // per-node completed-endpoint counter
__device__ int2  g_pairs[EE];              // (src, dst)
__device__ int   g_seq[2 * EE];            // per-endpoint rank among same-node endpoints
__device__ float g_Wf[KZ * AA];            // fused W_emb @ W_cls
__device__ float g_bf[AA];                 // fused bias

// ---------------- helpers ----------------
__device__ __forceinline__ int ld_acq(const int* p) {
    int v;
    asm volatile("ld.global.acquire.gpu.b32 %0, [%1];" : "=r"(v) : "l"(p));
    return v;
}
__device__ __forceinline__ void st_rel(int* p, int v) {
    asm volatile("st.global.release.gpu.b32 [%0], %1;" :: "l"(p), "r"(v) : "memory");
}
__device__ __forceinline__ void bar_group(int g) {
    asm volatile("bar.sync %0, 64;" :: "r"(g + 1) : "memory");
}
__device__ __forceinline__ float tanhx(float x) {   // HW tanh (sm_75+)
    float y;
    asm("tanh.approx.f32 %0, %1;" : "=f"(y) : "f"(x));
    return y;
}
__device__ __forceinline__ float sigf(float x) {    // sigmoid via HW tanh
    return fmaf(0.5f, tanhx(0.5f * x), 0.5f);
}

// ---------------- kernel 1: misc (zero done + pairs + fuse) — NO smem -----
__global__ void __launch_bounds__(256) misc_kernel(
    const int* __restrict__ eidx,
    const float* __restrict__ W_emb, const float* __restrict__ W_cls,
    const float* __restrict__ b_emb, const float* __restrict__ b_cls)
{
    int b = blockIdx.x;
    int t = threadIdx.x;
    if (b < MISC_ZERO_BLOCKS) {
        int n = b * 256 + t;              // endpoint id [0, 2*EE)
        int u = eidx[n];
        g_done[u] = 0;                    // racing same-value writes: benign
        if (n < EE) g_pairs[n] = make_int2(eidx[n], eidx[EE + n]);
    } else {
        int idx = (b - MISC_ZERO_BLOCKS) * 256 + t;
        if (idx < KZ * AA) {
            int k = idx / AA, a = idx % AA;
            float s = 0.f;
            #pragma unroll 8
            for (int c = 0; c < HH; c++) s = fmaf(W_emb[k * HH + c], W_cls[c * AA + a], s);
            g_Wf[idx] = s;
        } else if (idx < KZ * AA + AA) {
            int a = idx - KZ * AA;
            float s = b_cls[a];
            for (int c = 0; c < HH; c++) s = fmaf(b_emb[c], W_cls[c * AA + a], s);
            g_bf[a] = s;
        }
    }
}

// ---------------- kernel 2: seq — both endpoints of an event in one pass ---
__global__ void __launch_bounds__(256) seq_kernel(const int* __restrict__ eidx) {
    extern __shared__ int2 sp[];
    int t = threadIdx.x;
    for (int i = t; i < EE; i += 256)
        sp[i] = make_int2(eidx[i], eidx[EE + i]);
    __syncthreads();
    int lane = t & 31, w = t >> 5;
    for (int e = blockIdx.x * 8 + w; e < EE; e += gridDim.x * 8) {
        int2 pe = sp[e];
        int u0 = pe.x, u1 = pe.y;
        int c0 = 0, c1 = 0;
        for (int j = lane; j < e; j += 32) {
            int2 p = sp[j];
            c0 += (p.x == u0) + (p.y == u0);
            c1 += (p.x == u1) + (p.y == u1);
        }
        #pragma unroll
        for (int off = 16; off > 0; off >>= 1) {
            c0 += __shfl_down_sync(0xffffffffu, c0, off);
            c1 += __shfl_down_sync(0xffffffffu, c1, off);
        }
        if (lane == 0) {
            g_seq[2 * e] = c0;
            g_seq[2 * e + 1] = c1;
        }
    }
}

// ---------------- kernel 3: scan — pair-of-events per 64-thread group -----
// smem float offsets
#define O_WPM    0              // float2[64*64]: (w1+w2, w1-w2) per col
#define O_WC     8192           // float2[32*64]: comm weights, k-paired
#define O_WIH    12288          // permuted [k*64+col]*4+gate
#define O_WHH    28672
#define O_BMSG   45056
#define O_BLSTM  45120
#define O_TW     45376
#define O_TB     45408
#define O_GRP    45440
// group layout: HpA(128) HpB(128) SDA(128) SDB(128) CommA(64) CommB(64) MpA(128) MpB(128)
#define GRP_F    896
#define SCAN_SMEM_F (O_GRP + NGROUP * GRP_F)   // 54400 floats = 212.5 KB

struct ScanCtx {
    const float2* sWpm;
    const float2* sWc;
    const float*  sWihP;
    const float*  sWhhP;
    const float*  sbmsg;
    const float*  sblstm;
    const float*  stw;
    const float*  stb;
    const float*  eattr;
    const float*  etime;
};

// single-event path (used only for rare conflicting pairs)
__device__ __forceinline__ void process_one(
    int e, int lt, int g,
    float2* sHp, float2* sSD, float* sComm, float2* sMp, const ScanCtx& cx)
{
    int2 pr = g_pairs[e];
    int s0 = g_seq[2 * e], s1 = g_seq[2 * e + 1];
    bool w0 = (s0 > 0), w1 = (s1 > 0);
    if (w0 || w1) {
        int guard = 0;
        while (((w0 && ld_acq(&g_done[pr.x]) != s0) ||
                (w1 && ld_acq(&g_done[pr.y]) != s1)) && ++guard < (1 << 18)) {}
    }
    float hs = w0 ? __ldcg(&g_h[(size_t)pr.x * HH + lt]) : 0.f;
    float cs = w0 ? __ldcg(&g_c[(size_t)pr.x * HH + lt]) : 0.f;
    float hd = w1 ? __ldcg(&g_h[(size_t)pr.y * HH + lt]) : 0.f;
    float cd = w1 ? __ldcg(&g_c[(size_t)pr.y * HH + lt]) : 0.f;
    sHp[lt] = make_float2(hs, hd);
    sSD[lt] = make_float2(hs + hd, hs - hd);
    sComm[lt] = (lt < EADIM) ? cx.eattr[e * EADIM + lt]
              : cosf(__ldg(&cx.etime[e]) * cx.stw[lt - EADIM] + cx.stb[lt - EADIM]);
    bar_group(g);

    float u = 0.f, v = 0.f, ac = cx.sbmsg[lt];
    #pragma unroll 8
    for (int k = 0; k < 64; k++) {
        float2 sd = sSD[k];
        float2 w  = cx.sWpm[k * 64 + lt];
        u = fmaf(sd.x, w.x, u);
        v = fmaf(sd.y, w.y, v);
    }
    const float2* cm2 = (const float2*)sComm;
    #pragma unroll 8
    for (int k2 = 0; k2 < 32; k2++) {
        float2 c = cm2[k2];
        float2 w = cx.sWc[k2 * 64 + lt];
        ac = fmaf(c.x, w.x, ac);
        ac = fmaf(c.y, w.y, ac);
    }
    sMp[lt] = make_float2(fmaxf(ac + 0.5f * (u - v), 0.f),
                          fmaxf(ac + 0.5f * (u + v), 0.f));
    bar_group(g);

    float a00 = cx.sblstm[lt],       a01 = cx.sblstm[lt + 64];
    float a02 = cx.sblstm[lt + 128], a03 = cx.sblstm[lt + 192];
    float a10 = a00, a11 = a01, a12 = a02, a13 = a03;
    #pragma unroll 8
    for (int k = 0; k < 64; k++) {
        float2 m = sMp[k];
        float2 h = sHp[k];
        float4 wi = *(const float4*)&cx.sWihP[(k * 64 + lt) * 4];
        float4 wh = *(const float4*)&cx.sWhhP[(k * 64 + lt) * 4];
        a00 = fmaf(m.x, wi.x, a00); a01 = fmaf(m.x, wi.y, a01);
        a02 = fmaf(m.x, wi.z, a02); a03 = fmaf(m.x, wi.w, a03);
        a10 = fmaf(m.y, wi.x, a10); a11 = fmaf(m.y, wi.y, a11);
        a12 = fmaf(m.y, wi.z, a12); a13 = fmaf(m.y, wi.w, a13);
        a00 = fmaf(h.x, wh.x, a00); a01 = fmaf(h.x, wh.y, a01);
        a02 = fmaf(h.x, wh.z, a02); a03 = fmaf(h.x, wh.w, a03);
        a10 = fmaf(h.y, wh.x, a10); a11 = fmaf(h.y, wh.y, a11);
        a12 = fmaf(h.y, wh.z, a12); a13 = fmaf(h.y, wh.w, a13);
    }
    bool selfloop = (pr.x == pr.y);
    {
        float cn = sigf(a11) * cd + sigf(a10) * tanhx(a12);
        float hn = sigf(a13) * tanhx(cn);
        __stcg(&g_h[(size_t)pr.y * HH + lt], hn);
        __stcg(&g_c[(size_t)pr.y * HH + lt], cn);
    }
    if (!selfloop) {
        float cn = sigf(a01) * cs + sigf(a00) * tanhx(a02);
        float hn = sigf(a03) * tanhx(cn);
        __stcg(&g_h[(size_t)pr.x * HH + lt], hn);
        __stcg(&g_c[(size_t)pr.x * HH + lt], cn);
    }
    bar_group(g);
    if (lt == 0) {
        __threadfence();
        if (selfloop) {
            st_rel(&g_done[pr.x], s0 + 2);
        } else {
            st_rel(&g_done[pr.x], s0 + 1);
            st_rel(&g_done[pr.y], s1 + 1);
        }
    }
    bar_group(g);
}

__global__ void __launch_bounds__(BDIM, 1) scan_kernel(
    const float* __restrict__ Wmsg, const float* __restrict__ bmsg,
    const float* __restrict__ Wih,  const float* __restrict__ Whh,
    const float* __restrict__ blstm, const float* __restrict__ tw,
    const float* __restrict__ tb,   const float* __restrict__ eattr,
    const float* __restrict__ etime)
{
    extern __shared__ float sm[];
    int t = threadIdx.x;
    int g = t >> 6, lt = t & 63;

    ScanCtx cx;
    cx.sWpm  = (const float2*)(sm + O_WPM);
    cx.sWc   = (const float2*)(sm + O_WC);
    cx.sWihP = sm + O_WIH;
    cx.sWhhP = sm + O_WHH;
    cx.sbmsg = sm + O_BMSG;
    cx.sblstm= sm + O_BLSTM;
    cx.stw   = sm + O_TW;
    cx.stb   = sm + O_TB;
    cx.eattr = eattr;
    cx.etime = etime;

    float* grp = sm + O_GRP + g * GRP_F;
    float2* sHpA   = (float2*)grp;
    float2* sHpB   = (float2*)(grp + 128);
    float2* sSDA   = (float2*)(grp + 256);
    float2* sSDB   = (float2*)(grp + 384);
    float*  sCommA = grp + 512;
    float*  sCommB = grp + 576;
    float2* sMpA   = (float2*)(grp + 640);
    float2* sMpB   = (float2*)(grp + 768);

    // ---- load + transform weights (whole block) ----
    {
        float2* wWpm = (float2*)(sm + O_WPM);
        float2* wWc  = (float2*)(sm + O_WC);
        float*  wIh  = sm + O_WIH;
        float*  wHh  = sm + O_WHH;
        for (int i = t; i < 64 * 64; i += BDIM) {
            int k = i >> 6, col = i & 63;
            float w1 = Wmsg[k * HH + col];
            float w2 = Wmsg[(64 + k) * HH + col];
            wWpm[i] = make_float2(w1 + w2, w1 - w2);
        }
        for (int i = t; i < 32 * 64; i += BDIM) {
            int k2 = i >> 6, col = i & 63;
            wWc[i] = make_float2(Wmsg[(128 + 2 * k2) * HH + col],
                                 Wmsg[(129 + 2 * k2) * HH + col]);
        }
        for (int i = t; i < HH * G4; i += BDIM) {
            int k = i >> 8, j = i & 255;
            int p = ((k << 6) + (j & 63)) * 4 + (j >> 6);
            wIh[p] = Wih[i];
            wHh[p] = Whh[i];
        }
        if (t < HH)    (sm + O_BMSG)[t]  = bmsg[t];
        if (t < G4)    (sm + O_BLSTM)[t] = blstm[t];
        if (t < TEDIM) { (sm + O_TW)[t] = tw[t]; (sm + O_TB)[t] = tb[t]; }
    }
    __syncthreads();

    for (int p = blockIdx.x * NGROUP + g; p < EE / 2; p += NSTREAM) {
        int eA = 2 * p, eB = 2 * p + 1;
        int2 prA = g_pairs[eA], prB = g_pairs[eB];

        bool conflict = (prA.x == prB.x) | (prA.x == prB.y) |
                        (prA.y == prB.x) | (prA.y == prB.y);
        if (conflict) {    // rare: process sequentially
            process_one(eA, lt, g, sHpA, sSDA, sCommA, sMpA, cx);
            process_one(eB, lt, g, sHpA, sSDA, sCommA, sMpA, cx);
            continue;
        }

        int s0A = g_seq[2 * eA], s1A = g_seq[2 * eA + 1];
        int s0B = g_seq[2 * eB], s1B = g_seq[2 * eB + 1];
        bool wA0 = (s0A > 0), wA1 = (s1A > 0), wB0 = (s0B > 0), wB1 = (s1B > 0);
        if (wA0 | wA1 | wB0 | wB1) {
            int guard = 0;
            while (((wA0 && ld_acq(&g_done[prA.x]) != s0A) ||
                    (wA1 && ld_acq(&g_done[prA.y]) != s1A) ||
                    (wB0 && ld_acq(&g_done[prB.x]) != s0B) ||
                    (wB1 && ld_acq(&g_done[prB.y]) != s1B)) && ++guard < (1 << 18)) {}
        }

        // ---- states + comm for both events ----
        float hsA = wA0 ? __ldcg(&g_h[(size_t)prA.x * HH + lt]) : 0.f;
        float csA = wA0 ? __ldcg(&g_c[(size_t)prA.x * HH + lt]) : 0.f;
        float hdA = wA1 ? __ldcg(&g_h[(size_t)prA.y * HH + lt]) : 0.f;
        float cdA = wA1 ? __ldcg(&g_c[(size_t)prA.y * HH + lt]) : 0.f;
        float hsB = wB0 ? __ldcg(&g_h[(size_t)prB.x * HH + lt]) : 0.f;
        float csB = wB0 ? __ldcg(&g_c[(size_t)prB.x * HH + lt]) : 0.f;
        float hdB = wB1 ? __ldcg(&g_h[(size_t)prB.y * HH + lt]) : 0.f;
        float cdB = wB1 ? __ldcg(&g_c[(size_t)prB.y * HH + lt]) : 0.f;
        sHpA[lt] = make_float2(hsA, hdA);
        sSDA[lt] = make_float2(hsA + hdA, hsA - hdA);
        sHpB[lt] = make_float2(hsB, hdB);
        sSDB[lt] = make_float2(hsB + hdB, hsB - hdB);
        if (lt < EADIM) {
            sCommA[lt] = eattr[eA * EADIM + lt];
            sCommB[lt] = eattr[eB * EADIM + lt];
        } else {
            int i = lt - EADIM;
            sCommA[lt] = cosf(__ldg(&etime[eA]) * cx.stw[i] + cx.stb[i]);
            sCommB[lt] = cosf(__ldg(&etime[eB]) * cx.stw[i] + cx.stb[i]);
        }
        bar_group(g);

        // ---- gemm1 for both events, weights loaded once ----
        float uA = 0.f, vA = 0.f, uB = 0.f, vB = 0.f;
        float acA = cx.sbmsg[lt], acB = acA;
        #pragma unroll 8
        for (int k = 0; k < 64; k++) {
            float2 w  = cx.sWpm[k * 64 + lt];
            float2 a = sSDA[k];
            float2 b = sSDB[k];
            uA = fmaf(a.x, w.x, uA); vA = fmaf(a.y, w.y, vA);
            uB = fmaf(b.x, w.x, uB); vB = fmaf(b.y, w.y, vB);
        }
        const float2* cmA = (const float2*)sCommA;
        const float2* cmB = (const float2*)sCommB;
        #pragma unroll 8
        for (int k2 = 0; k2 < 32; k2++) {
            float2 w = cx.sWc[k2 * 64 + lt];
            float2 a = cmA[k2];
            float2 b = cmB[k2];
            acA = fmaf(a.x, w.x, acA); acA = fmaf(a.y, w.y, acA);
            acB = fmaf(b.x, w.x, acB); acB = fmaf(b.y, w.y, acB);
        }
        sMpA[lt] = make_float2(fmaxf(acA + 0.5f * (uA - vA), 0.f),
                               fmaxf(acA + 0.5f * (uA + vA), 0.f));
        sMpB[lt] = make_float2(fmaxf(acB + 0.5f * (uB - vB), 0.f),
                               fmaxf(acB + 0.5f * (uB + vB), 0.f));
        bar_group(g);

        // ---- gemm2 for both events, weights loaded once (16 accumulators) ----
        float bl0 = cx.sblstm[lt],       bl1 = cx.sblstm[lt + 64];
        float bl2 = cx.sblstm[lt + 128], bl3 = cx.sblstm[lt + 192];
        float aA00 = bl0, aA01 = bl1, aA02 = bl2, aA03 = bl3;
        float aA10 = bl0, aA11 = bl1, aA12 = bl2, aA13 = bl3;
        float aB00 = bl0, aB01 = bl1, aB02 = bl2, aB03 = bl3;
        float aB10 = bl0, aB11 = bl1, aB12 = bl2, aB13 = bl3;
        #pragma unroll 4
        for (int k = 0; k < 64; k++) {
            float4 wi = *(const float4*)&cx.sWihP[(k * 64 + lt) * 4];
            float4 wh = *(const float4*)&cx.sWhhP[(k * 64 + lt) * 4];
            float2 mA = sMpA[k]; float2 hA = sHpA[k];
            float2 mB = sMpB[k]; float2 hB = sHpB[k];
            aA00 = fmaf(mA.x, wi.x, aA00); aA01 = fmaf(mA.x, wi.y, aA01);
            aA02 = fmaf(mA.x, wi.z, aA02); aA03 = fmaf(mA.x, wi.w, aA03);
            aA10 = fmaf(mA.y, wi.x, aA10); aA11 = fmaf(mA.y, wi.y, aA11);
            aA12 = fmaf(mA.y, wi.z, aA12); aA13 = fmaf(mA.y, wi.w, aA13);
            aA00 = fmaf(hA.x, wh.x, aA00); aA01 = fmaf(hA.x, wh.y, aA01);
            aA02 = fmaf(hA.x, wh.z, aA02); aA03 = fmaf(hA.x, wh.w, aA03);
            aA10 = fmaf(hA.y, wh.x, aA10); aA11 = fmaf(hA.y, wh.y, aA11);
            aA12 = fmaf(hA.y, wh.z, aA12); aA13 = fmaf(hA.y, wh.w, aA13);
            aB00 = fmaf(mB.x, wi.x, aB00); aB01 = fmaf(mB.x, wi.y, aB01);
            aB02 = fmaf(mB.x, wi.z, aB02); aB03 = fmaf(mB.x, wi.w, aB03);
            aB10 = fmaf(mB.y, wi.x, aB10); aB11 = fmaf(mB.y, wi.y, aB11);
            aB12 = fmaf(mB.y, wi.z, aB12); aB13 = fmaf(mB.y, wi.w, aB13);
            aB00 = fmaf(hB.x, wh.x, aB00); aB01 = fmaf(hB.x, wh.y, aB01);
            aB02 = fmaf(hB.x, wh.z, aB02); aB03 = fmaf(hB.x, wh.w, aB03);
            aB10 = fmaf(hB.y, wh.x, aB10); aB11 = fmaf(hB.y, wh.y, aB11);
            aB12 = fmaf(hB.y, wh.z, aB12); aB13 = fmaf(hB.y, wh.w, aB13);
        }

        // ---- elementwise + stores (dst row wins on per-event self-loop) ----
        bool slA = (prA.x == prA.y), slB = (prB.x == prB.y);
        {
            float cn = sigf(aA11) * cdA + sigf(aA10) * tanhx(aA12);
            float hn = sigf(aA13) * tanhx(cn);
            __stcg(&g_h[(size_t)prA.y * HH + lt], hn);
            __stcg(&g_c[(size_t)prA.y * HH + lt], cn);
        }
        if (!slA) {
            float cn = sigf(aA01) * csA + sigf(aA00) * tanhx(aA02);
            float hn = sigf(aA03) * tanhx(cn);
            __stcg(&g_h[(size_t)prA.x * HH + lt], hn);
            __stcg(&g_c[(size_t)prA.x * HH + lt], cn);
        }
        {
            float cn = sigf(aB11) * cdB + sigf(aB10) * tanhx(aB12);
            float hn = sigf(aB13) * tanhx(cn);
            __stcg(&g_h[(size_t)prB.y * HH + lt], hn);
            __stcg(&g_c[(size_t)prB.y * HH + lt], cn);
        }
        if (!slB) {
            float cn = sigf(aB01) * csB + sigf(aB00) * tanhx(aB02);
            float hn = sigf(aB03) * tanhx(cn);
            __stcg(&g_h[(size_t)prB.x * HH + lt], hn);
            __stcg(&g_c[(size_t)prB.x * HH + lt], cn);
        }
        bar_group(g);

        if (lt == 0) {
            __threadfence();
            if (slA) st_rel(&g_done[prA.x], s0A + 2);
            else { st_rel(&g_done[prA.x], s0A + 1); st_rel(&g_done[prA.y], s1A + 1); }
            if (slB) st_rel(&g_done[prB.x], s0B + 2);
            else { st_rel(&g_done[prB.x], s0B + 1); st_rel(&g_done[prB.y], s1B + 1); }
        }
        bar_group(g);
    }
}

// ---------------- kernel 4: epilogue — 4 events/warp, float4 row loads -----
// dyn smem layout (floats): sWf[KZ*AA] | sbf[64] | sCat[8][4][KZ]
#define EP_O_WF   0
#define EP_O_BF   (KZ * AA)                 // 9600
#define EP_O_CAT  (EP_O_BF + 64)            // 9664
#define EP_SMEM_F (EP_O_CAT + 8 * 4 * KZ)   // 15808 floats = 63232 B

__global__ void __launch_bounds__(256) epilogue_kernel(const float* __restrict__ x,
                                                       const int* __restrict__ eidx,
                                                       float* __restrict__ out) {
    extern __shared__ float esm[];
    float* sWf = esm + EP_O_WF;
    float* sbf = esm + EP_O_BF;
    int t = threadIdx.x;
    for (int i = t; i < KZ * AA; i += 256) sWf[i] = g_Wf[i];
    if (t < AA) sbf[t] = g_bf[t];
    __syncthreads();
    int lane = t & 31, w = t >> 5;
    float* sc = esm + EP_O_CAT + w * 4 * KZ;
    int e0 = (blockIdx.x * 8 + w) * 4;        // 4 events per warp
    // gather [h||x] rows (coalesced per row)
    #pragma unroll
    for (int j = 0; j < 4; j++) {
        int d = eidx[EE + e0 + j];
        const float* hv = &g_h[(size_t)d * HH];
        const float* xv = &x[(size_t)d * DFEAT];
        #pragma unroll
        for (int q = 0; q < 6; q++) {
            int k = lane + q * 32;
            sc[j * KZ + k] = (k < HH) ? hv[k] : xv[k - HH];
        }
    }
    __syncwarp();
    bool hi = (lane < AA - 32);
    float b0 = sbf[lane], b1 = hi ? sbf[lane + 32] : 0.f;
    float a00 = b0, a01 = b1, a10 = b0, a11 = b1;
    float a20 = b0, a21 = b1, a30 = b0, a31 = b1;
    for (int k4 = 0; k4 < KZ; k4 += 4) {
        float4 v0 = *(const float4*)&sc[0 * KZ + k4];
        float4 v1 = *(const float4*)&sc[1 * KZ + k4];
        float4 v2 = *(const float4*)&sc[2 * KZ + k4];
        float4 v3 = *(const float4*)&sc[3 * KZ + k4];
        #pragma unroll
        for (int i = 0; i < 4; i++) {
            float wA = sWf[(k4 + i) * AA + lane];
            float wB = hi ? sWf[(k4 + i) * AA + lane + 32] : 0.f;
            float e0v = (&v0.x)[i], e1v = (&v1.x)[i];
            float e2v = (&v2.x)[i], e3v = (&v3.x)[i];
            a00 = fmaf(e0v, wA, a00); a01 = fmaf(e0v, wB, a01);
            a10 = fmaf(e1v, wA, a10); a11 = fmaf(e1v, wB, a11);
            a20 = fmaf(e2v, wA, a20); a21 = fmaf(e2v, wB, a21);
            a30 = fmaf(e3v, wA, a30); a31 = fmaf(e3v, wB, a31);
        }
    }
    out[(size_t)(e0 + 0) * AA + lane] = a00;
    out[(size_t)(e0 + 1) * AA + lane] = a10;
    out[(size_t)(e0 + 2) * AA + lane] = a20;
    out[(size_t)(e0 + 3) * AA + lane] = a30;
    if (hi) {
        out[(size_t)(e0 + 0) * AA + lane + 32] = a01;
        out[(size_t)(e0 + 1) * AA + lane + 32] = a11;
        out[(size_t)(e0 + 2) * AA + lane + 32] = a21;
        out[(size_t)(e0 + 3) * AA + lane + 32] = a31;
    }
}

// ---------------- launch ----------------
extern "C" void kernel_launch(void* const* d_in, const int* in_sizes, int n_in,
                              void* d_out, int out_size) {
    const float* x      = (const float*)d_in[0];
    const int*   eidx   = (const int*)  d_in[1];
    const float* eattr  = (const float*)d_in[2];
    const float* etime  = (const float*)d_in[3];
    const float* time_w = (const float*)d_in[4];
    const float* time_b = (const float*)d_in[5];
    const float* W_msg  = (const float*)d_in[6];
    const float* b_msg  = (const float*)d_in[7];
    const float* W_ih   = (const float*)d_in[8];
    const float* W_hh   = (const float*)d_in[9];
    const float* b_lstm = (const float*)d_in[10];
    const float* W_emb  = (const float*)d_in[11];
    const float* b_emb  = (const float*)d_in[12];
    const float* W_cls  = (const float*)d_in[13];
    const float* b_cls  = (const float*)d_in[14];
    float* out = (float*)d_out;

    cudaFuncSetAttribute(seq_kernel, cudaFuncAttributeMaxDynamicSharedMemorySize,
                         EE * (int)sizeof(int2));
    cudaFuncSetAttribute(scan_kernel, cudaFuncAttributeMaxDynamicSharedMemorySize,
                         SCAN_SMEM_F * (int)sizeof(float));
    cudaFuncSetAttribute(epilogue_kernel, cudaFuncAttributeMaxDynamicSharedMemorySize,
                         EP_SMEM_F * (int)sizeof(float));

    misc_kernel<<<MISC_BLOCKS, 256>>>(eidx, W_emb, W_cls, b_emb, b_cls);
    seq_kernel<<<128, 256, EE * sizeof(int2)>>>(eidx);
    scan_kernel<<<SCAN_BLOCKS, BDIM, SCAN_SMEM_F * sizeof(float)>>>(
        W_msg, b_msg, W_ih, W_hh, b_lstm, time_w, time_b, eattr, etime);
    epilogue_kernel<<<256, 256, EP_SMEM_F * sizeof(float)>>>(x, eidx, out);
}